// round 11
// baseline (speedup 1.0000x reference)
#include <cuda_runtime.h>
#include <cuda_bf16.h>
#include <cstdint>

#define B_ 8
#define C_ 256
#define D_ 32
#define N_ 4096

// ---------------------------------------------------------------------------
// Scratch (allocation-free rule: __device__ globals)
// ---------------------------------------------------------------------------
__device__ __nv_bfloat16  g_Qh[(size_t)B_ * N_ * D_];    // [b][n][d] bf16 hi
__device__ __nv_bfloat16  g_Ql[(size_t)B_ * N_ * D_];    // [b][n][d] bf16 lo
__device__ __nv_bfloat16  g_Kh[(size_t)B_ * N_ * D_];    // [b][m][d] bf16 hi
__device__ __nv_bfloat16  g_Kl[(size_t)B_ * N_ * D_];    // [b][m][d] bf16 lo
__device__ __nv_bfloat16  g_Vhi[(size_t)B_ * C_ * N_];   // [b][c][m] bf16 hi
__device__ __nv_bfloat16  g_Vlo[(size_t)B_ * C_ * N_];   // [b][c][m] bf16 lo
__device__ __nv_bfloat16  g_P[(size_t)B_ * N_ * N_];     // [b][n][m] exp(s) bf16 (unshifted)
__device__ float          g_L[B_ * N_];                  // row sum of quantized p

// ---------------------------------------------------------------------------
// Portable PTX helpers (mma.sync / ldmatrix / cp.async only — no 'a'-gated ops)
// ---------------------------------------------------------------------------
__device__ __forceinline__ uint32_t smem_u32(const void* p) {
    uint32_t a;
    asm("{ .reg .u64 t; cvta.to.shared.u64 t, %1; cvt.u32.u64 %0, t; }" : "=r"(a) : "l"(p));
    return a;
}
__device__ __forceinline__ void cp16(uint32_t s, const void* g) {
    asm volatile("cp.async.cg.shared.global [%0], [%1], 16;" :: "r"(s), "l"(g));
}
__device__ __forceinline__ void cp_commit() {
    asm volatile("cp.async.commit_group;" ::: "memory");
}
__device__ __forceinline__ void cp_wait0() {
    asm volatile("cp.async.wait_group 0;" ::: "memory");
}
__device__ __forceinline__ void cp_wait1() {
    asm volatile("cp.async.wait_group 1;" ::: "memory");
}
__device__ __forceinline__ void ldm_x4(uint32_t* r, uint32_t addr) {
    asm volatile("ldmatrix.sync.aligned.m8n8.x4.shared.b16 {%0,%1,%2,%3}, [%4];"
                 : "=r"(r[0]), "=r"(r[1]), "=r"(r[2]), "=r"(r[3]) : "r"(addr));
}
__device__ __forceinline__ void mma16816(float* d, const uint32_t* a, const uint32_t* b) {
    asm volatile(
        "mma.sync.aligned.m16n8k16.row.col.f32.bf16.bf16.f32 "
        "{%0,%1,%2,%3}, {%4,%5,%6,%7}, {%8,%9}, {%0,%1,%2,%3};"
        : "+f"(d[0]), "+f"(d[1]), "+f"(d[2]), "+f"(d[3])
        : "r"(a[0]), "r"(a[1]), "r"(a[2]), "r"(a[3]), "r"(b[0]), "r"(b[1]));
}

// ---------------------------------------------------------------------------
// Kernel 1: Q/K projection -> bf16 hi/lo, [b][n][32] rows of 64B.  (unchanged)
// ---------------------------------------------------------------------------
__global__ __launch_bounds__(256)
void qk_proj_kernel(const float* __restrict__ x,
                    const float* __restrict__ Wq, const float* __restrict__ bq,
                    const float* __restrict__ Wk, const float* __restrict__ bk) {
    extern __shared__ float sW[];               // [0:8192) Wq, [8192:16384) Wk
    const int b    = blockIdx.y;
    const int tid  = threadIdx.x;
    const int part = tid >> 6;
    const int n    = blockIdx.x * 64 + (tid & 63);

    for (int i = tid; i < D_ * C_; i += 256) {
        sW[i]           = Wq[i];
        sW[D_ * C_ + i] = Wk[i];
    }
    __syncthreads();

    float qa[8], ka[8];
#pragma unroll
    for (int j = 0; j < 8; j++) { qa[j] = 0.f; ka[j] = 0.f; }

    const float* wq = sW + part * 8 * C_;
    const float* wk = sW + D_ * C_ + part * 8 * C_;
    const float* xp = x + (size_t)b * C_ * N_ + n;

    for (int c = 0; c < C_; c++) {
        float xv = xp[(size_t)c * N_];
#pragma unroll
        for (int j = 0; j < 8; j++) {
            qa[j] += wq[j * C_ + c] * xv;
            ka[j] += wk[j * C_ + c] * xv;
        }
    }

    const size_t base = ((size_t)b * N_ + n) * D_ + part * 8;
    __nv_bfloat16 qh8[8], ql8[8], kh8[8], kl8[8];
#pragma unroll
    for (int j = 0; j < 8; j++) {
        float qv = qa[j] + bq[part * 8 + j];
        float kv = ka[j] + bk[part * 8 + j];
        qh8[j] = __float2bfloat16(qv);
        ql8[j] = __float2bfloat16(qv - __bfloat162float(qh8[j]));
        kh8[j] = __float2bfloat16(kv);
        kl8[j] = __float2bfloat16(kv - __bfloat162float(kh8[j]));
    }
    *(uint4*)(g_Qh + base) = *(uint4*)qh8;
    *(uint4*)(g_Ql + base) = *(uint4*)ql8;
    *(uint4*)(g_Kh + base) = *(uint4*)kh8;
    *(uint4*)(g_Kl + base) = *(uint4*)kl8;
}

// ---------------------------------------------------------------------------
// Kernel 2: V projection -> split bf16 (hi + lo residual).  (unchanged)
// ---------------------------------------------------------------------------
__global__ void v_proj_kernel(const float* __restrict__ x,
                              const float* __restrict__ Wv, const float* __restrict__ bv) {
    __shared__ float sA[16][68];
    __shared__ float sB[16][64];
    const int b  = blockIdx.z;
    const int e0 = blockIdx.y * 64;
    const int n0 = blockIdx.x * 64;
    const int tid = threadIdx.x;
    const int tx = tid & 15, ty = tid >> 4;
    const int e_l = tid >> 2, cf = tid & 3;
    const int c_l = tid >> 4, nf = tid & 15;

    float acc[4][4] = {};

    for (int c0 = 0; c0 < C_; c0 += 16) {
        float4 w4 = *(const float4*)(Wv + (e0 + e_l) * C_ + c0 + cf * 4);
        sA[cf * 4 + 0][e_l] = w4.x;
        sA[cf * 4 + 1][e_l] = w4.y;
        sA[cf * 4 + 2][e_l] = w4.z;
        sA[cf * 4 + 3][e_l] = w4.w;
        *(float4*)&sB[c_l][nf * 4] =
            *(const float4*)(x + ((size_t)(b * C_ + c0 + c_l)) * N_ + n0 + nf * 4);
        __syncthreads();
#pragma unroll
        for (int kk = 0; kk < 16; kk++) {
            float4 a4 = *(const float4*)&sA[kk][ty * 4];
            float4 b4 = *(const float4*)&sB[kk][tx * 4];
            acc[0][0] += a4.x * b4.x; acc[0][1] += a4.x * b4.y; acc[0][2] += a4.x * b4.z; acc[0][3] += a4.x * b4.w;
            acc[1][0] += a4.y * b4.x; acc[1][1] += a4.y * b4.y; acc[1][2] += a4.y * b4.z; acc[1][3] += a4.y * b4.w;
            acc[2][0] += a4.z * b4.x; acc[2][1] += a4.z * b4.y; acc[2][2] += a4.z * b4.z; acc[2][3] += a4.z * b4.w;
            acc[3][0] += a4.w * b4.x; acc[3][1] += a4.w * b4.y; acc[3][2] += a4.w * b4.z; acc[3][3] += a4.w * b4.w;
        }
        __syncthreads();
    }
#pragma unroll
    for (int i = 0; i < 4; i++) {
        int e = e0 + ty * 4 + i;
        float bias = bv[e];
        size_t base = ((size_t)(b * C_ + e)) * N_ + n0 + tx * 4;
#pragma unroll
        for (int j = 0; j < 4; j += 2) {
            float v0 = acc[i][j] + bias, v1 = acc[i][j + 1] + bias;
            __nv_bfloat16 h0 = __float2bfloat16(v0);
            __nv_bfloat16 h1 = __float2bfloat16(v1);
            __nv_bfloat162 hp; hp.x = h0; hp.y = h1;
            *(__nv_bfloat162*)(g_Vhi + base + j) = hp;
            __nv_bfloat162 lp;
            lp.x = __float2bfloat16(v0 - __bfloat162float(h0));
            lp.y = __float2bfloat16(v1 - __bfloat162float(h1));
            *(__nv_bfloat162*)(g_Vlo + base + j) = lp;
        }
    }
}

// ---------------------------------------------------------------------------
// Kernel 3: HMMA scores + exp + quantize + L.  (unchanged from R8)
// ---------------------------------------------------------------------------
#define S_NIT   (N_ / 128)
#define SO_QH   512
#define SO_QL   (SO_QH + 4096)
#define SO_K    (SO_QL + 4096)
#define S_TOTAL (SO_K + 2 * 16384)

__device__ __forceinline__ void s_load_k(uint32_t sbase, int b, int m0, int tid) {
    const char* gkh = (const char*)g_Kh + ((size_t)b * N_ + m0) * 64;
    const char* gkl = (const char*)g_Kl + ((size_t)b * N_ + m0) * 64;
#pragma unroll
    for (int i = 0; i < 2; i++) {
        int id = tid + i * 256;
        int row = id >> 2, ch = id & 3;
        int phys = ch ^ ((row >> 1) & 3);
        uint32_t so = row * 64 + phys * 16;
        uint32_t go = row * 64 + ch * 16;
        cp16(sbase + so, gkh + go);
        cp16(sbase + 8192 + so, gkl + go);
    }
}

__global__ __launch_bounds__(256, 2)
void scores_p_kernel() {
    extern __shared__ char ssm[];
    const uint32_t sb = smem_u32(ssm);
    float* smL = (float*)ssm;
    const int b    = blockIdx.y;
    const int n0   = blockIdx.x * 64;
    const int tid  = threadIdx.x;
    const int lane = tid & 31;
    const int wn   = (tid >> 5) & 1;
    const int wm   = tid >> 6;

    if (tid < 64) smL[tid] = 0.f;

    {
        int row = tid >> 2, ch = tid & 3;
        int phys = ch ^ ((row >> 1) & 3);
        uint32_t so = row * 64 + phys * 16;
        uint32_t go = row * 64 + ch * 16;
        const char* gqh = (const char*)g_Qh + ((size_t)b * N_ + n0) * 64;
        const char* gql = (const char*)g_Ql + ((size_t)b * N_ + n0) * 64;
        cp16(sb + SO_QH + so, gqh + go);
        cp16(sb + SO_QL + so, gql + go);
    }
    s_load_k(sb + SO_K, b, 0, tid);
    cp_commit();
    cp_wait0();
    __syncthreads();

    uint32_t aqh[2][2][4], aql[2][2][4];
#pragma unroll
    for (int mt = 0; mt < 2; mt++)
#pragma unroll
        for (int kk = 0; kk < 2; kk++) {
            uint32_t row = wn * 32 + mt * 16 + (lane & 15);
            uint32_t chl = 2 * kk + (lane >> 4);
            uint32_t phys = chl ^ ((row >> 1) & 3);
            ldm_x4(aqh[mt][kk], sb + SO_QH + row * 64 + phys * 16);
            ldm_x4(aql[mt][kk], sb + SO_QL + row * 64 + phys * 16);
        }

    float Lp[4] = {0.f, 0.f, 0.f, 0.f};

    for (int kt = 0; kt < S_NIT; kt++) {
        if (kt + 1 < S_NIT) {
            s_load_k(sb + SO_K + ((kt + 1) & 1) * 16384, b, (kt + 1) * 128, tid);
            cp_commit();
            cp_wait1();
        } else {
            cp_wait0();
        }
        __syncthreads();

        const uint32_t kbase = sb + SO_K + (kt & 1) * 16384;
        float acc[2][4][4];
#pragma unroll
        for (int mt = 0; mt < 2; mt++)
#pragma unroll
            for (int nt = 0; nt < 4; nt++)
#pragma unroll
                for (int r = 0; r < 4; r++) acc[mt][nt][r] = 0.f;

#pragma unroll
        for (int kk = 0; kk < 2; kk++) {
            uint32_t khf[2][4], klf[2][4];
#pragma unroll
            for (int nt2 = 0; nt2 < 2; nt2++) {
                uint32_t row = wm * 32 + nt2 * 16 + (lane & 7) + ((lane >> 4) << 3);
                uint32_t chl = 2 * kk + ((lane >> 3) & 1);
                uint32_t phys = chl ^ ((row >> 1) & 3);
                uint32_t ad = kbase + row * 64 + phys * 16;
                ldm_x4(khf[nt2], ad);
                ldm_x4(klf[nt2], ad + 8192);
            }
#pragma unroll
            for (int mt = 0; mt < 2; mt++)
#pragma unroll
                for (int nt = 0; nt < 4; nt++) {
                    const uint32_t* bh = &khf[nt >> 1][(nt & 1) * 2];
                    const uint32_t* bl = &klf[nt >> 1][(nt & 1) * 2];
                    mma16816(acc[mt][nt], aqh[mt][kk], bh);
                    mma16816(acc[mt][nt], aqh[mt][kk], bl);
                    mma16816(acc[mt][nt], aql[mt][kk], bh);
                }
        }

        const int m0 = kt * 128;
#pragma unroll
        for (int mt = 0; mt < 2; mt++) {
            const int r0 = n0 + wn * 32 + mt * 16 + (lane >> 2);
            const size_t rb0 = ((size_t)b * N_ + r0) * N_;
            const size_t rb1 = rb0 + (size_t)8 * N_;
#pragma unroll
            for (int nt = 0; nt < 4; nt++) {
                const int mc = m0 + wm * 32 + nt * 8 + (lane & 3) * 2;
                float e0 = __expf(acc[mt][nt][0]);
                float e1 = __expf(acc[mt][nt][1]);
                float e2 = __expf(acc[mt][nt][2]);
                float e3 = __expf(acc[mt][nt][3]);
                __nv_bfloat162 p01 = __floats2bfloat162_rn(e0, e1);
                __nv_bfloat162 p23 = __floats2bfloat162_rn(e2, e3);
                Lp[mt * 2 + 0] += __bfloat162float(p01.x) + __bfloat162float(p01.y);
                Lp[mt * 2 + 1] += __bfloat162float(p23.x) + __bfloat162float(p23.y);
                *(uint32_t*)(g_P + rb0 + mc) = *(uint32_t*)&p01;
                *(uint32_t*)(g_P + rb1 + mc) = *(uint32_t*)&p23;
            }
        }
        __syncthreads();
    }

#pragma unroll
    for (int i = 0; i < 4; i++) {
        Lp[i] += __shfl_xor_sync(0xffffffffu, Lp[i], 1);
        Lp[i] += __shfl_xor_sync(0xffffffffu, Lp[i], 2);
    }
    if ((lane & 3) == 0) {
        int rbase = wn * 32 + (lane >> 2);
        atomicAdd(&smL[rbase + 0],  Lp[0]);
        atomicAdd(&smL[rbase + 8],  Lp[1]);
        atomicAdd(&smL[rbase + 16], Lp[2]);
        atomicAdd(&smL[rbase + 24], Lp[3]);
    }
    __syncthreads();
    if (tid < 64) g_L[b * N_ + n0 + tid] = smL[tid];
}

// ---------------------------------------------------------------------------
// Kernel 4: AV GEMM, CTA = 256(c) x 128(n), 512 thr (8c x 2n warps),
// 3-stage cp.async, ONE __syncthreads per k-iteration.
// Stage layout: Vhi[256x64B] @0, Vlo @16384, P[128x64B] @32768 (40KB/stage).
// ---------------------------------------------------------------------------
#define AV_OFF0   1024
#define AV_STAGE  40960
#define AV_TOTAL  (AV_OFF0 + 3 * AV_STAGE)
#define NKT       (N_ / 32)

__device__ __forceinline__ void av_load_stage(uint32_t sbase,
                                              const char* gVhi, const char* gVlo,
                                              const char* gP, int kt, int tid) {
    const size_t gcol = (size_t)kt * 64;
#pragma unroll
    for (int i = 0; i < 2; i++) {
        int id  = tid + i * 512;
        int row = id >> 2, ch = id & 3;
        int phys = ch ^ ((row >> 1) & 3);
        uint32_t so = row * 64 + phys * 16;
        size_t   go = (size_t)row * (N_ * 2) + gcol + ch * 16;
        cp16(sbase + so,         gVhi + go);
        cp16(sbase + 16384 + so, gVlo + go);
    }
    {
        int row = tid >> 2, ch = tid & 3;
        int phys = ch ^ ((row >> 1) & 3);
        uint32_t so = row * 64 + phys * 16;
        size_t   go = (size_t)row * (N_ * 2) + gcol + ch * 16;
        cp16(sbase + 32768 + so, gP + go);
    }
}

__global__ __launch_bounds__(512, 1)
void av_gemm_kernel(const float* __restrict__ x, float* __restrict__ out) {
    extern __shared__ char dsm[];
    const uint32_t sb = smem_u32(dsm);
    const int tid  = threadIdx.x;
    const int wid  = tid >> 5;
    const int lane = tid & 31;
    const int wr   = wid & 7;     // c block (32 rows of 256)
    const int wc   = wid >> 3;    // n block (64 cols of 128)
    const int n0 = blockIdx.x * 128;
    const int b  = blockIdx.z;

    float* sm_inv = (float*)dsm;
    if (tid < 128) sm_inv[tid] = 1.0f / g_L[b * N_ + n0 + tid];

    const char* gVhi = (const char*)g_Vhi + ((size_t)b * C_) * N_ * 2;
    const char* gVlo = (const char*)g_Vlo + ((size_t)b * C_) * N_ * 2;
    const char* gP   = (const char*)g_P   + ((size_t)b * N_ + n0) * N_ * 2;

    uint32_t rowA[2], swzA[2];
#pragma unroll
    for (int mt = 0; mt < 2; mt++) {
        rowA[mt] = wr * 32 + mt * 16 + (lane & 15);
        swzA[mt] = (rowA[mt] >> 1) & 3;
    }
    const uint32_t khA = lane >> 4;
    uint32_t rowB[4], swzB[4];
#pragma unroll
    for (int nt2 = 0; nt2 < 4; nt2++) {
        rowB[nt2] = wc * 64 + nt2 * 16 + (lane & 7) + ((lane >> 4) << 3);
        swzB[nt2] = (rowB[nt2] >> 1) & 3;
    }
    const uint32_t khB = (lane >> 3) & 1;

    float acc[2][8][4];
#pragma unroll
    for (int mt = 0; mt < 2; mt++)
#pragma unroll
        for (int nt = 0; nt < 8; nt++)
#pragma unroll
            for (int r = 0; r < 4; r++) acc[mt][nt][r] = 0.f;

    av_load_stage(sb + AV_OFF0,            gVhi, gVlo, gP, 0, tid); cp_commit();
    av_load_stage(sb + AV_OFF0 + AV_STAGE, gVhi, gVlo, gP, 1, tid); cp_commit();

    int bufc = 0;   // buffer index of stage kt
    for (int kt = 0; kt < NKT; kt++) {
        cp_wait1();            // stage kt landed (only kt+1 may remain in flight)
        __syncthreads();       // all warps done with stage kt-1's buffer
        {
            int bufn = bufc + 2; if (bufn >= 3) bufn -= 3;   // == (kt-1)%3, now free
            if (kt + 2 < NKT)
                av_load_stage(sb + AV_OFF0 + bufn * AV_STAGE, gVhi, gVlo, gP, kt + 2, tid);
            cp_commit();       // unconditional: keeps group counting uniform
        }

        const uint32_t buf = sb + AV_OFF0 + bufc * AV_STAGE;
#pragma unroll
        for (int ks = 0; ks < 2; ks++) {
            uint32_t bb[4][4];
#pragma unroll
            for (int nt2 = 0; nt2 < 4; nt2++) {
                uint32_t ch = ((ks * 2 + khB) ^ swzB[nt2]) * 16;
                ldm_x4(bb[nt2], buf + 32768 + rowB[nt2] * 64 + ch);
            }
#pragma unroll
            for (int mt = 0; mt < 2; mt++) {
                uint32_t ah[4], al[4];
                uint32_t ch = ((ks * 2 + khA) ^ swzA[mt]) * 16;
                uint32_t ad = buf + rowA[mt] * 64 + ch;
                ldm_x4(ah, ad);
                ldm_x4(al, ad + 16384);
#pragma unroll
                for (int nt = 0; nt < 8; nt++) {
                    const uint32_t* bf = &bb[nt >> 1][(nt & 1) * 2];
                    mma16816(acc[mt][nt], ah, bf);
                    mma16816(acc[mt][nt], al, bf);
                }
            }
        }
        if (++bufc == 3) bufc = 0;
    }

    // Epilogue: scale by 1/L, add residual, store fp32.
#pragma unroll
    for (int mt = 0; mt < 2; mt++) {
        int cA = wr * 32 + mt * 16 + (lane >> 2);
#pragma unroll
        for (int nt = 0; nt < 8; nt++) {
            int nl = wc * 64 + nt * 8 + (lane & 3) * 2;
            float i0 = sm_inv[nl], i1 = sm_inv[nl + 1];
            size_t o0 = ((size_t)(b * C_ + cA)) * N_ + n0 + nl;
            float2 xv = *(const float2*)(x + o0);
            float2 ov;
            ov.x = acc[mt][nt][0] * i0 + xv.x;
            ov.y = acc[mt][nt][1] * i1 + xv.y;
            *(float2*)(out + o0) = ov;
            size_t o1 = o0 + (size_t)8 * N_;
            float2 xv2 = *(const float2*)(x + o1);
            float2 ov2;
            ov2.x = acc[mt][nt][2] * i0 + xv2.x;
            ov2.y = acc[mt][nt][3] * i1 + xv2.y;
            *(float2*)(out + o1) = ov2;
        }
    }
}

// ---------------------------------------------------------------------------
extern "C" void kernel_launch(void* const* d_in, const int* in_sizes, int n_in,
                              void* d_out, int out_size) {
    const float* x  = (const float*)d_in[0];
    const float* Wq = (const float*)d_in[1];
    const float* bq = (const float*)d_in[2];
    const float* Wk = (const float*)d_in[3];
    const float* bk = (const float*)d_in[4];
    const float* Wv = (const float*)d_in[5];
    const float* bv = (const float*)d_in[6];
    float* out = (float*)d_out;

    const int qk_smem = 2 * D_ * C_ * (int)sizeof(float);  // 64 KB

    cudaFuncSetAttribute(qk_proj_kernel,  cudaFuncAttributeMaxDynamicSharedMemorySize, qk_smem);
    cudaFuncSetAttribute(scores_p_kernel, cudaFuncAttributeMaxDynamicSharedMemorySize, S_TOTAL);
    cudaFuncSetAttribute(av_gemm_kernel,  cudaFuncAttributeMaxDynamicSharedMemorySize, AV_TOTAL);

    qk_proj_kernel<<<dim3(N_ / 64, B_), 256, qk_smem>>>(x, Wq, bq, Wk, bk);
    v_proj_kernel<<<dim3(N_ / 64, C_ / 64, B_), 256>>>(x, Wv, bv);
    scores_p_kernel<<<dim3(N_ / 64, B_), 256, S_TOTAL>>>();
    av_gemm_kernel<<<dim3(N_ / 128, 1, B_), 512, AV_TOTAL>>>(x, out);
}

// round 12
// speedup vs baseline: 1.3794x; 1.3794x over previous
#include <cuda_runtime.h>
#include <cuda_fp16.h>
#include <cstdint>

#define B_ 8
#define C_ 256
#define D_ 32
#define N_ 4096

#define SHIFT_ 16.0f

// ---------------------------------------------------------------------------
// Scratch (allocation-free rule: __device__ globals)
// ---------------------------------------------------------------------------
__device__ __half  g_Qf[(size_t)B_ * N_ * D_];    // [b][n][d] fp16
__device__ __half  g_Kf[(size_t)B_ * N_ * D_];    // [b][m][d] fp16
__device__ __half  g_Vf[(size_t)B_ * C_ * N_];    // [b][c][m] fp16
__device__ __half  g_P[(size_t)B_ * N_ * N_];     // [b][n][m] exp(s-16) fp16
__device__ float   g_L[B_ * N_];                  // row sum of quantized p

// ---------------------------------------------------------------------------
// Portable PTX helpers
// ---------------------------------------------------------------------------
__device__ __forceinline__ uint32_t smem_u32(const void* p) {
    uint32_t a;
    asm("{ .reg .u64 t; cvta.to.shared.u64 t, %1; cvt.u32.u64 %0, t; }" : "=r"(a) : "l"(p));
    return a;
}
__device__ __forceinline__ void cp16(uint32_t s, const void* g) {
    asm volatile("cp.async.cg.shared.global [%0], [%1], 16;" :: "r"(s), "l"(g));
}
__device__ __forceinline__ void cp_commit() {
    asm volatile("cp.async.commit_group;" ::: "memory");
}
__device__ __forceinline__ void cp_wait0() {
    asm volatile("cp.async.wait_group 0;" ::: "memory");
}
__device__ __forceinline__ void cp_wait1() {
    asm volatile("cp.async.wait_group 1;" ::: "memory");
}
__device__ __forceinline__ void cp_wait2() {
    asm volatile("cp.async.wait_group 2;" ::: "memory");
}
__device__ __forceinline__ void ldm_x4(uint32_t* r, uint32_t addr) {
    asm volatile("ldmatrix.sync.aligned.m8n8.x4.shared.b16 {%0,%1,%2,%3}, [%4];"
                 : "=r"(r[0]), "=r"(r[1]), "=r"(r[2]), "=r"(r[3]) : "r"(addr));
}
__device__ __forceinline__ void mma16816h(float* d, const uint32_t* a, const uint32_t* b) {
    asm volatile(
        "mma.sync.aligned.m16n8k16.row.col.f32.f16.f16.f32 "
        "{%0,%1,%2,%3}, {%4,%5,%6,%7}, {%8,%9}, {%0,%1,%2,%3};"
        : "+f"(d[0]), "+f"(d[1]), "+f"(d[2]), "+f"(d[3])
        : "r"(a[0]), "r"(a[1]), "r"(a[2]), "r"(a[3]), "r"(b[0]), "r"(b[1]));
}

// ---------------------------------------------------------------------------
// Kernel 1: Q/K projection -> fp16, [b][n][32] rows of 64B.
// ---------------------------------------------------------------------------
__global__ __launch_bounds__(256)
void qk_proj_kernel(const float* __restrict__ x,
                    const float* __restrict__ Wq, const float* __restrict__ bq,
                    const float* __restrict__ Wk, const float* __restrict__ bk) {
    extern __shared__ float sW[];               // [0:8192) Wq, [8192:16384) Wk
    const int b    = blockIdx.y;
    const int tid  = threadIdx.x;
    const int part = tid >> 6;
    const int n    = blockIdx.x * 64 + (tid & 63);

    for (int i = tid; i < D_ * C_; i += 256) {
        sW[i]           = Wq[i];
        sW[D_ * C_ + i] = Wk[i];
    }
    __syncthreads();

    float qa[8], ka[8];
#pragma unroll
    for (int j = 0; j < 8; j++) { qa[j] = 0.f; ka[j] = 0.f; }

    const float* wq = sW + part * 8 * C_;
    const float* wk = sW + D_ * C_ + part * 8 * C_;
    const float* xp = x + (size_t)b * C_ * N_ + n;

    for (int c = 0; c < C_; c++) {
        float xv = xp[(size_t)c * N_];
#pragma unroll
        for (int j = 0; j < 8; j++) {
            qa[j] += wq[j * C_ + c] * xv;
            ka[j] += wk[j * C_ + c] * xv;
        }
    }

    const size_t base = ((size_t)b * N_ + n) * D_ + part * 8;
    __half q8[8], k8[8];
#pragma unroll
    for (int j = 0; j < 8; j++) {
        q8[j] = __float2half_rn(qa[j] + bq[part * 8 + j]);
        k8[j] = __float2half_rn(ka[j] + bk[part * 8 + j]);
    }
    *(uint4*)(g_Qf + base) = *(uint4*)q8;
    *(uint4*)(g_Kf + base) = *(uint4*)k8;
}

// ---------------------------------------------------------------------------
// Kernel 2: V projection -> fp16.
// ---------------------------------------------------------------------------
__global__ void v_proj_kernel(const float* __restrict__ x,
                              const float* __restrict__ Wv, const float* __restrict__ bv) {
    __shared__ float sA[16][68];
    __shared__ float sB[16][64];
    const int b  = blockIdx.z;
    const int e0 = blockIdx.y * 64;
    const int n0 = blockIdx.x * 64;
    const int tid = threadIdx.x;
    const int tx = tid & 15, ty = tid >> 4;
    const int e_l = tid >> 2, cf = tid & 3;
    const int c_l = tid >> 4, nf = tid & 15;

    float acc[4][4] = {};

    for (int c0 = 0; c0 < C_; c0 += 16) {
        float4 w4 = *(const float4*)(Wv + (e0 + e_l) * C_ + c0 + cf * 4);
        sA[cf * 4 + 0][e_l] = w4.x;
        sA[cf * 4 + 1][e_l] = w4.y;
        sA[cf * 4 + 2][e_l] = w4.z;
        sA[cf * 4 + 3][e_l] = w4.w;
        *(float4*)&sB[c_l][nf * 4] =
            *(const float4*)(x + ((size_t)(b * C_ + c0 + c_l)) * N_ + n0 + nf * 4);
        __syncthreads();
#pragma unroll
        for (int kk = 0; kk < 16; kk++) {
            float4 a4 = *(const float4*)&sA[kk][ty * 4];
            float4 b4 = *(const float4*)&sB[kk][tx * 4];
            acc[0][0] += a4.x * b4.x; acc[0][1] += a4.x * b4.y; acc[0][2] += a4.x * b4.z; acc[0][3] += a4.x * b4.w;
            acc[1][0] += a4.y * b4.x; acc[1][1] += a4.y * b4.y; acc[1][2] += a4.y * b4.z; acc[1][3] += a4.y * b4.w;
            acc[2][0] += a4.z * b4.x; acc[2][1] += a4.z * b4.y; acc[2][2] += a4.z * b4.z; acc[2][3] += a4.z * b4.w;
            acc[3][0] += a4.w * b4.x; acc[3][1] += a4.w * b4.y; acc[3][2] += a4.w * b4.z; acc[3][3] += a4.w * b4.w;
        }
        __syncthreads();
    }
#pragma unroll
    for (int i = 0; i < 4; i++) {
        int e = e0 + ty * 4 + i;
        float bias = bv[e];
        size_t base = ((size_t)(b * C_ + e)) * N_ + n0 + tx * 4;
        __half2 h01 = __floats2half2_rn(acc[i][0] + bias, acc[i][1] + bias);
        __half2 h23 = __floats2half2_rn(acc[i][2] + bias, acc[i][3] + bias);
        *(__half2*)(g_Vf + base)     = h01;
        *(__half2*)(g_Vf + base + 2) = h23;
    }
}

// ---------------------------------------------------------------------------
// Kernel 3: HMMA fp16 scores + shifted exp + quantize + L.
//   p = fp16(exp(q.k - 16)), L = sum of quantized p (shift cancels at /L).
// CTA 256 thr / 8 warps (2 n x 4 m); n-block 64; m-tiles of 128; cp.async x2.
// ---------------------------------------------------------------------------
#define S_NIT   (N_ / 128)
#define SO_Q    512
#define SO_K    (SO_Q + 4096)
#define S_TOTAL (SO_K + 2 * 8192)

__device__ __forceinline__ void s_load_k(uint32_t sbase, int b, int m0, int tid) {
    const char* gk = (const char*)g_Kf + ((size_t)b * N_ + m0) * 64;
#pragma unroll
    for (int i = 0; i < 2; i++) {
        int id = tid + i * 256;
        int row = id >> 2, ch = id & 3;
        int phys = ch ^ ((row >> 1) & 3);
        cp16(sbase + row * 64 + phys * 16, gk + row * 64 + ch * 16);
    }
}

__global__ __launch_bounds__(256, 3)
void scores_p_kernel() {
    extern __shared__ char ssm[];
    const uint32_t sb = smem_u32(ssm);
    float* smL = (float*)ssm;
    const int b    = blockIdx.y;
    const int n0   = blockIdx.x * 64;
    const int tid  = threadIdx.x;
    const int lane = tid & 31;
    const int wn   = (tid >> 5) & 1;
    const int wm   = tid >> 6;

    if (tid < 64) smL[tid] = 0.f;

    {
        int row = tid >> 2, ch = tid & 3;
        int phys = ch ^ ((row >> 1) & 3);
        const char* gq = (const char*)g_Qf + ((size_t)b * N_ + n0) * 64;
        cp16(sb + SO_Q + row * 64 + phys * 16, gq + row * 64 + ch * 16);
    }
    s_load_k(sb + SO_K, b, 0, tid);
    cp_commit();
    cp_wait0();
    __syncthreads();

    uint32_t aq[2][2][4];
#pragma unroll
    for (int mt = 0; mt < 2; mt++)
#pragma unroll
        for (int kk = 0; kk < 2; kk++) {
            uint32_t row = wn * 32 + mt * 16 + (lane & 15);
            uint32_t chl = 2 * kk + (lane >> 4);
            uint32_t phys = chl ^ ((row >> 1) & 3);
            ldm_x4(aq[mt][kk], sb + SO_Q + row * 64 + phys * 16);
        }

    float Lp[4] = {0.f, 0.f, 0.f, 0.f};

    for (int kt = 0; kt < S_NIT; kt++) {
        if (kt + 1 < S_NIT) {
            s_load_k(sb + SO_K + ((kt + 1) & 1) * 8192, b, (kt + 1) * 128, tid);
            cp_commit();
            cp_wait1();
        } else {
            cp_wait0();
        }
        __syncthreads();

        const uint32_t kbase = sb + SO_K + (kt & 1) * 8192;
        float acc[2][4][4];
#pragma unroll
        for (int mt = 0; mt < 2; mt++)
#pragma unroll
            for (int nt = 0; nt < 4; nt++)
#pragma unroll
                for (int r = 0; r < 4; r++) acc[mt][nt][r] = 0.f;

#pragma unroll
        for (int kk = 0; kk < 2; kk++) {
            uint32_t kf[2][4];
#pragma unroll
            for (int nt2 = 0; nt2 < 2; nt2++) {
                uint32_t row = wm * 32 + nt2 * 16 + (lane & 7) + ((lane >> 4) << 3);
                uint32_t chl = 2 * kk + ((lane >> 3) & 1);
                uint32_t phys = chl ^ ((row >> 1) & 3);
                ldm_x4(kf[nt2], kbase + row * 64 + phys * 16);
            }
#pragma unroll
            for (int mt = 0; mt < 2; mt++)
#pragma unroll
                for (int nt = 0; nt < 4; nt++)
                    mma16816h(acc[mt][nt], aq[mt][kk], &kf[nt >> 1][(nt & 1) * 2]);
        }

        const int m0 = kt * 128;
#pragma unroll
        for (int mt = 0; mt < 2; mt++) {
            const int r0 = n0 + wn * 32 + mt * 16 + (lane >> 2);
            const size_t rb0 = ((size_t)b * N_ + r0) * N_;
            const size_t rb1 = rb0 + (size_t)8 * N_;
#pragma unroll
            for (int nt = 0; nt < 4; nt++) {
                const int mc = m0 + wm * 32 + nt * 8 + (lane & 3) * 2;
                float e0 = __expf(acc[mt][nt][0] - SHIFT_);
                float e1 = __expf(acc[mt][nt][1] - SHIFT_);
                float e2 = __expf(acc[mt][nt][2] - SHIFT_);
                float e3 = __expf(acc[mt][nt][3] - SHIFT_);
                __half2 p01 = __floats2half2_rn(e0, e1);
                __half2 p23 = __floats2half2_rn(e2, e3);
                Lp[mt * 2 + 0] += __low2float(p01) + __high2float(p01);
                Lp[mt * 2 + 1] += __low2float(p23) + __high2float(p23);
                *(uint32_t*)(g_P + rb0 + mc) = *(uint32_t*)&p01;
                *(uint32_t*)(g_P + rb1 + mc) = *(uint32_t*)&p23;
            }
        }
        __syncthreads();
    }

#pragma unroll
    for (int i = 0; i < 4; i++) {
        Lp[i] += __shfl_xor_sync(0xffffffffu, Lp[i], 1);
        Lp[i] += __shfl_xor_sync(0xffffffffu, Lp[i], 2);
    }
    if ((lane & 3) == 0) {
        int rbase = wn * 32 + (lane >> 2);
        atomicAdd(&smL[rbase + 0],  Lp[0]);
        atomicAdd(&smL[rbase + 8],  Lp[1]);
        atomicAdd(&smL[rbase + 16], Lp[2]);
        atomicAdd(&smL[rbase + 24], Lp[3]);
    }
    __syncthreads();
    if (tid < 64) g_L[b * N_ + n0 + tid] = smL[tid];
}

// ---------------------------------------------------------------------------
// Kernel 4: AV GEMM fp16 (single V buffer), R8 geometry 128x128, 256 thr,
// 2 CTAs/SM, 4-stage cp.async (16KB/stage), one sync per kt.
// ---------------------------------------------------------------------------
#define AV_OFF0   1024
#define AV_STAGE  16384
#define AV_TOTAL  (AV_OFF0 + 4 * AV_STAGE)
#define NKT       (N_ / 32)

__device__ __forceinline__ void av_load_stage(uint32_t sbase,
                                              const char* gV, const char* gP,
                                              int kt, int tid) {
    const size_t gcol = (size_t)kt * 64;
#pragma unroll
    for (int i = 0; i < 2; i++) {
        int id  = tid + i * 256;
        int row = id >> 2, ch = id & 3;
        int phys = ch ^ ((row >> 1) & 3);
        uint32_t so = row * 64 + phys * 16;
        size_t   go = (size_t)row * (N_ * 2) + gcol + ch * 16;
        cp16(sbase + so,        gV + go);
        cp16(sbase + 8192 + so, gP + go);
    }
}

__global__ __launch_bounds__(256, 2)
void av_gemm_kernel(const float* __restrict__ x, float* __restrict__ out) {
    extern __shared__ char dsm[];
    const uint32_t sb = smem_u32(dsm);
    const int tid  = threadIdx.x;
    const int wid  = tid >> 5;
    const int lane = tid & 31;
    const int wr   = wid & 3;     // c block (32 of 128)
    const int wc   = wid >> 2;    // n block (64 of 128)
    const int n0 = blockIdx.x * 128;
    const int c0 = blockIdx.y * 128;
    const int b  = blockIdx.z;

    float* sm_inv = (float*)dsm;
    if (tid < 128) sm_inv[tid] = 1.0f / g_L[b * N_ + n0 + tid];

    const char* gV = (const char*)g_Vf + ((size_t)(b * C_ + c0)) * N_ * 2;
    const char* gP = (const char*)g_P  + ((size_t)b * N_ + n0) * N_ * 2;

    uint32_t rowA[2], swzA[2];
#pragma unroll
    for (int mt = 0; mt < 2; mt++) {
        rowA[mt] = wr * 32 + mt * 16 + (lane & 15);
        swzA[mt] = (rowA[mt] >> 1) & 3;
    }
    const uint32_t khA = lane >> 4;
    uint32_t rowB[4], swzB[4];
#pragma unroll
    for (int nt2 = 0; nt2 < 4; nt2++) {
        rowB[nt2] = wc * 64 + nt2 * 16 + (lane & 7) + ((lane >> 4) << 3);
        swzB[nt2] = (rowB[nt2] >> 1) & 3;
    }
    const uint32_t khB = (lane >> 3) & 1;

    float acc[2][8][4];
#pragma unroll
    for (int mt = 0; mt < 2; mt++)
#pragma unroll
        for (int nt = 0; nt < 8; nt++)
#pragma unroll
            for (int r = 0; r < 4; r++) acc[mt][nt][r] = 0.f;

    av_load_stage(sb + AV_OFF0,                gV, gP, 0, tid); cp_commit();
    av_load_stage(sb + AV_OFF0 +     AV_STAGE, gV, gP, 1, tid); cp_commit();
    av_load_stage(sb + AV_OFF0 + 2 * AV_STAGE, gV, gP, 2, tid); cp_commit();

    for (int kt = 0; kt < NKT; kt++) {
        cp_wait2();            // stage kt landed (kt+1, kt+2 may remain in flight)
        __syncthreads();       // all warps finished stage kt-1's buffer
        if (kt + 3 < NKT)
            av_load_stage(sb + AV_OFF0 + ((kt + 3) & 3) * AV_STAGE, gV, gP, kt + 3, tid);
        cp_commit();           // unconditional: uniform group counting

        const uint32_t buf = sb + AV_OFF0 + (kt & 3) * AV_STAGE;
#pragma unroll
        for (int ks = 0; ks < 2; ks++) {
            uint32_t bb[4][4];
#pragma unroll
            for (int nt2 = 0; nt2 < 4; nt2++) {
                uint32_t ch = ((ks * 2 + khB) ^ swzB[nt2]) * 16;
                ldm_x4(bb[nt2], buf + 8192 + rowB[nt2] * 64 + ch);
            }
#pragma unroll
            for (int mt = 0; mt < 2; mt++) {
                uint32_t ah[4];
                uint32_t ch = ((ks * 2 + khA) ^ swzA[mt]) * 16;
                ldm_x4(ah, buf + rowA[mt] * 64 + ch);
#pragma unroll
                for (int nt = 0; nt < 8; nt++)
                    mma16816h(acc[mt][nt], ah, &bb[nt >> 1][(nt & 1) * 2]);
            }
        }
    }

    // Epilogue: scale by 1/L, add residual, store fp32.
#pragma unroll
    for (int mt = 0; mt < 2; mt++) {
        int cA = c0 + wr * 32 + mt * 16 + (lane >> 2);
#pragma unroll
        for (int nt = 0; nt < 8; nt++) {
            int nl = wc * 64 + nt * 8 + (lane & 3) * 2;
            float i0 = sm_inv[nl], i1 = sm_inv[nl + 1];
            size_t o0 = ((size_t)(b * C_ + cA)) * N_ + n0 + nl;
            float2 xv = *(const float2*)(x + o0);
            float2 ov;
            ov.x = acc[mt][nt][0] * i0 + xv.x;
            ov.y = acc[mt][nt][1] * i1 + xv.y;
            *(float2*)(out + o0) = ov;
            size_t o1 = o0 + (size_t)8 * N_;
            float2 xv2 = *(const float2*)(x + o1);
            float2 ov2;
            ov2.x = acc[mt][nt][2] * i0 + xv2.x;
            ov2.y = acc[mt][nt][3] * i1 + xv2.y;
            *(float2*)(out + o1) = ov2;
        }
    }
}

// ---------------------------------------------------------------------------
extern "C" void kernel_launch(void* const* d_in, const int* in_sizes, int n_in,
                              void* d_out, int out_size) {
    const float* x  = (const float*)d_in[0];
    const float* Wq = (const float*)d_in[1];
    const float* bq = (const float*)d_in[2];
    const float* Wk = (const float*)d_in[3];
    const float* bk = (const float*)d_in[4];
    const float* Wv = (const float*)d_in[5];
    const float* bv = (const float*)d_in[6];
    float* out = (float*)d_out;

    const int qk_smem = 2 * D_ * C_ * (int)sizeof(float);  // 64 KB

    cudaFuncSetAttribute(qk_proj_kernel,  cudaFuncAttributeMaxDynamicSharedMemorySize, qk_smem);
    cudaFuncSetAttribute(scores_p_kernel, cudaFuncAttributeMaxDynamicSharedMemorySize, S_TOTAL);
    cudaFuncSetAttribute(av_gemm_kernel,  cudaFuncAttributeMaxDynamicSharedMemorySize, AV_TOTAL);

    qk_proj_kernel<<<dim3(N_ / 64, B_), 256, qk_smem>>>(x, Wq, bq, Wk, bk);
    v_proj_kernel<<<dim3(N_ / 64, C_ / 64, B_), 256>>>(x, Wv, bv);
    scores_p_kernel<<<dim3(N_ / 64, B_), 256, S_TOTAL>>>();
    av_gemm_kernel<<<dim3(N_ / 128, C_ / 128, B_), 256, AV_TOTAL>>>(x, out);
}

// round 13
// speedup vs baseline: 1.5088x; 1.0939x over previous
#include <cuda_runtime.h>
#include <cuda_fp16.h>
#include <cstdint>

#define B_ 8
#define C_ 256
#define D_ 32
#define N_ 4096

#define SHIFT_ 16.0f

// ---------------------------------------------------------------------------
// Scratch (allocation-free rule: __device__ globals)
// ---------------------------------------------------------------------------
__device__ __half  g_Qf[(size_t)B_ * N_ * D_];    // [b][n][d] fp16
__device__ __half  g_Kf[(size_t)B_ * N_ * D_];    // [b][m][d] fp16
__device__ __half  g_Vf[(size_t)B_ * C_ * N_];    // [b][c][m] fp16
__device__ __half  g_P[(size_t)B_ * N_ * N_];     // [b][n][m] exp(s-16) fp16
__device__ float   g_L[B_ * N_];                  // row sum of quantized p

// ---------------------------------------------------------------------------
// Portable PTX helpers
// ---------------------------------------------------------------------------
__device__ __forceinline__ uint32_t smem_u32(const void* p) {
    uint32_t a;
    asm("{ .reg .u64 t; cvta.to.shared.u64 t, %1; cvt.u32.u64 %0, t; }" : "=r"(a) : "l"(p));
    return a;
}
__device__ __forceinline__ void cp16(uint32_t s, const void* g) {
    asm volatile("cp.async.cg.shared.global [%0], [%1], 16;" :: "r"(s), "l"(g));
}
__device__ __forceinline__ void cp_commit() {
    asm volatile("cp.async.commit_group;" ::: "memory");
}
__device__ __forceinline__ void cp_wait0() {
    asm volatile("cp.async.wait_group 0;" ::: "memory");
}
__device__ __forceinline__ void cp_wait1() {
    asm volatile("cp.async.wait_group 1;" ::: "memory");
}
__device__ __forceinline__ void cp_wait2() {
    asm volatile("cp.async.wait_group 2;" ::: "memory");
}
__device__ __forceinline__ void ldm_x4(uint32_t* r, uint32_t addr) {
    asm volatile("ldmatrix.sync.aligned.m8n8.x4.shared.b16 {%0,%1,%2,%3}, [%4];"
                 : "=r"(r[0]), "=r"(r[1]), "=r"(r[2]), "=r"(r[3]) : "r"(addr));
}
__device__ __forceinline__ void mma16816h(float* d, const uint32_t* a, const uint32_t* b) {
    asm volatile(
        "mma.sync.aligned.m16n8k16.row.col.f32.f16.f16.f32 "
        "{%0,%1,%2,%3}, {%4,%5,%6,%7}, {%8,%9}, {%0,%1,%2,%3};"
        : "+f"(d[0]), "+f"(d[1]), "+f"(d[2]), "+f"(d[3])
        : "r"(a[0]), "r"(a[1]), "r"(a[2]), "r"(a[3]), "r"(b[0]), "r"(b[1]));
}

// ---------------------------------------------------------------------------
// Kernel 1: Q/K projection -> fp16, [b][n][32] rows of 64B.  (unchanged)
// ---------------------------------------------------------------------------
__global__ __launch_bounds__(256)
void qk_proj_kernel(const float* __restrict__ x,
                    const float* __restrict__ Wq, const float* __restrict__ bq,
                    const float* __restrict__ Wk, const float* __restrict__ bk) {
    extern __shared__ float sW[];               // [0:8192) Wq, [8192:16384) Wk
    const int b    = blockIdx.y;
    const int tid  = threadIdx.x;
    const int part = tid >> 6;
    const int n    = blockIdx.x * 64 + (tid & 63);

    for (int i = tid; i < D_ * C_; i += 256) {
        sW[i]           = Wq[i];
        sW[D_ * C_ + i] = Wk[i];
    }
    __syncthreads();

    float qa[8], ka[8];
#pragma unroll
    for (int j = 0; j < 8; j++) { qa[j] = 0.f; ka[j] = 0.f; }

    const float* wq = sW + part * 8 * C_;
    const float* wk = sW + D_ * C_ + part * 8 * C_;
    const float* xp = x + (size_t)b * C_ * N_ + n;

    for (int c = 0; c < C_; c++) {
        float xv = xp[(size_t)c * N_];
#pragma unroll
        for (int j = 0; j < 8; j++) {
            qa[j] += wq[j * C_ + c] * xv;
            ka[j] += wk[j * C_ + c] * xv;
        }
    }

    const size_t base = ((size_t)b * N_ + n) * D_ + part * 8;
    __half q8[8], k8[8];
#pragma unroll
    for (int j = 0; j < 8; j++) {
        q8[j] = __float2half_rn(qa[j] + bq[part * 8 + j]);
        k8[j] = __float2half_rn(ka[j] + bk[part * 8 + j]);
    }
    *(uint4*)(g_Qf + base) = *(uint4*)q8;
    *(uint4*)(g_Kf + base) = *(uint4*)k8;
}

// ---------------------------------------------------------------------------
// Kernel 2: V projection -> fp16.  (unchanged)
// ---------------------------------------------------------------------------
__global__ void v_proj_kernel(const float* __restrict__ x,
                              const float* __restrict__ Wv, const float* __restrict__ bv) {
    __shared__ float sA[16][68];
    __shared__ float sB[16][64];
    const int b  = blockIdx.z;
    const int e0 = blockIdx.y * 64;
    const int n0 = blockIdx.x * 64;
    const int tid = threadIdx.x;
    const int tx = tid & 15, ty = tid >> 4;
    const int e_l = tid >> 2, cf = tid & 3;
    const int c_l = tid >> 4, nf = tid & 15;

    float acc[4][4] = {};

    for (int c0 = 0; c0 < C_; c0 += 16) {
        float4 w4 = *(const float4*)(Wv + (e0 + e_l) * C_ + c0 + cf * 4);
        sA[cf * 4 + 0][e_l] = w4.x;
        sA[cf * 4 + 1][e_l] = w4.y;
        sA[cf * 4 + 2][e_l] = w4.z;
        sA[cf * 4 + 3][e_l] = w4.w;
        *(float4*)&sB[c_l][nf * 4] =
            *(const float4*)(x + ((size_t)(b * C_ + c0 + c_l)) * N_ + n0 + nf * 4);
        __syncthreads();
#pragma unroll
        for (int kk = 0; kk < 16; kk++) {
            float4 a4 = *(const float4*)&sA[kk][ty * 4];
            float4 b4 = *(const float4*)&sB[kk][tx * 4];
            acc[0][0] += a4.x * b4.x; acc[0][1] += a4.x * b4.y; acc[0][2] += a4.x * b4.z; acc[0][3] += a4.x * b4.w;
            acc[1][0] += a4.y * b4.x; acc[1][1] += a4.y * b4.y; acc[1][2] += a4.y * b4.z; acc[1][3] += a4.y * b4.w;
            acc[2][0] += a4.z * b4.x; acc[2][1] += a4.z * b4.y; acc[2][2] += a4.z * b4.z; acc[2][3] += a4.z * b4.w;
            acc[3][0] += a4.w * b4.x; acc[3][1] += a4.w * b4.y; acc[3][2] += a4.w * b4.z; acc[3][3] += a4.w * b4.w;
        }
        __syncthreads();
    }
#pragma unroll
    for (int i = 0; i < 4; i++) {
        int e = e0 + ty * 4 + i;
        float bias = bv[e];
        size_t base = ((size_t)(b * C_ + e)) * N_ + n0 + tx * 4;
        __half2 h01 = __floats2half2_rn(acc[i][0] + bias, acc[i][1] + bias);
        __half2 h23 = __floats2half2_rn(acc[i][2] + bias, acc[i][3] + bias);
        *(__half2*)(g_Vf + base)     = h01;
        *(__half2*)(g_Vf + base + 2) = h23;
    }
}

// ---------------------------------------------------------------------------
// Kernel 3: HMMA fp16 scores + shifted exp + quantize + L.  (unchanged)
// ---------------------------------------------------------------------------
#define S_NIT   (N_ / 128)
#define SO_Q    512
#define SO_K    (SO_Q + 4096)
#define S_TOTAL (SO_K + 2 * 8192)

__device__ __forceinline__ void s_load_k(uint32_t sbase, int b, int m0, int tid) {
    const char* gk = (const char*)g_Kf + ((size_t)b * N_ + m0) * 64;
#pragma unroll
    for (int i = 0; i < 2; i++) {
        int id = tid + i * 256;
        int row = id >> 2, ch = id & 3;
        int phys = ch ^ ((row >> 1) & 3);
        cp16(sbase + row * 64 + phys * 16, gk + row * 64 + ch * 16);
    }
}

__global__ __launch_bounds__(256, 3)
void scores_p_kernel() {
    extern __shared__ char ssm[];
    const uint32_t sb = smem_u32(ssm);
    float* smL = (float*)ssm;
    const int b    = blockIdx.y;
    const int n0   = blockIdx.x * 64;
    const int tid  = threadIdx.x;
    const int lane = tid & 31;
    const int wn   = (tid >> 5) & 1;
    const int wm   = tid >> 6;

    if (tid < 64) smL[tid] = 0.f;

    {
        int row = tid >> 2, ch = tid & 3;
        int phys = ch ^ ((row >> 1) & 3);
        const char* gq = (const char*)g_Qf + ((size_t)b * N_ + n0) * 64;
        cp16(sb + SO_Q + row * 64 + phys * 16, gq + row * 64 + ch * 16);
    }
    s_load_k(sb + SO_K, b, 0, tid);
    cp_commit();
    cp_wait0();
    __syncthreads();

    uint32_t aq[2][2][4];
#pragma unroll
    for (int mt = 0; mt < 2; mt++)
#pragma unroll
        for (int kk = 0; kk < 2; kk++) {
            uint32_t row = wn * 32 + mt * 16 + (lane & 15);
            uint32_t chl = 2 * kk + (lane >> 4);
            uint32_t phys = chl ^ ((row >> 1) & 3);
            ldm_x4(aq[mt][kk], sb + SO_Q + row * 64 + phys * 16);
        }

    float Lp[4] = {0.f, 0.f, 0.f, 0.f};

    for (int kt = 0; kt < S_NIT; kt++) {
        if (kt + 1 < S_NIT) {
            s_load_k(sb + SO_K + ((kt + 1) & 1) * 8192, b, (kt + 1) * 128, tid);
            cp_commit();
            cp_wait1();
        } else {
            cp_wait0();
        }
        __syncthreads();

        const uint32_t kbase = sb + SO_K + (kt & 1) * 8192;
        float acc[2][4][4];
#pragma unroll
        for (int mt = 0; mt < 2; mt++)
#pragma unroll
            for (int nt = 0; nt < 4; nt++)
#pragma unroll
                for (int r = 0; r < 4; r++) acc[mt][nt][r] = 0.f;

#pragma unroll
        for (int kk = 0; kk < 2; kk++) {
            uint32_t kf[2][4];
#pragma unroll
            for (int nt2 = 0; nt2 < 2; nt2++) {
                uint32_t row = wm * 32 + nt2 * 16 + (lane & 7) + ((lane >> 4) << 3);
                uint32_t chl = 2 * kk + ((lane >> 3) & 1);
                uint32_t phys = chl ^ ((row >> 1) & 3);
                ldm_x4(kf[nt2], kbase + row * 64 + phys * 16);
            }
#pragma unroll
            for (int mt = 0; mt < 2; mt++)
#pragma unroll
                for (int nt = 0; nt < 4; nt++)
                    mma16816h(acc[mt][nt], aq[mt][kk], &kf[nt >> 1][(nt & 1) * 2]);
        }

        const int m0 = kt * 128;
#pragma unroll
        for (int mt = 0; mt < 2; mt++) {
            const int r0 = n0 + wn * 32 + mt * 16 + (lane >> 2);
            const size_t rb0 = ((size_t)b * N_ + r0) * N_;
            const size_t rb1 = rb0 + (size_t)8 * N_;
#pragma unroll
            for (int nt = 0; nt < 4; nt++) {
                const int mc = m0 + wm * 32 + nt * 8 + (lane & 3) * 2;
                float e0 = __expf(acc[mt][nt][0] - SHIFT_);
                float e1 = __expf(acc[mt][nt][1] - SHIFT_);
                float e2 = __expf(acc[mt][nt][2] - SHIFT_);
                float e3 = __expf(acc[mt][nt][3] - SHIFT_);
                __half2 p01 = __floats2half2_rn(e0, e1);
                __half2 p23 = __floats2half2_rn(e2, e3);
                Lp[mt * 2 + 0] += __low2float(p01) + __high2float(p01);
                Lp[mt * 2 + 1] += __low2float(p23) + __high2float(p23);
                *(uint32_t*)(g_P + rb0 + mc) = *(uint32_t*)&p01;
                *(uint32_t*)(g_P + rb1 + mc) = *(uint32_t*)&p23;
            }
        }
        __syncthreads();
    }

#pragma unroll
    for (int i = 0; i < 4; i++) {
        Lp[i] += __shfl_xor_sync(0xffffffffu, Lp[i], 1);
        Lp[i] += __shfl_xor_sync(0xffffffffu, Lp[i], 2);
    }
    if ((lane & 3) == 0) {
        int rbase = wn * 32 + (lane >> 2);
        atomicAdd(&smL[rbase + 0],  Lp[0]);
        atomicAdd(&smL[rbase + 8],  Lp[1]);
        atomicAdd(&smL[rbase + 16], Lp[2]);
        atomicAdd(&smL[rbase + 24], Lp[3]);
    }
    __syncthreads();
    if (tid < 64) g_L[b * N_ + n0 + tid] = smL[tid];
}

// ---------------------------------------------------------------------------
// Kernel 4: AV GEMM fp16, CTA 128x128 with 128 thr / 4 warps (2c x 2n),
// warp tile 64x64 (4mt x 8nt) -> 0.038 smem B/FLOP. 4-stage cp.async.
// ---------------------------------------------------------------------------
#define AV_OFF0   1024
#define AV_STAGE  16384
#define AV_TOTAL  (AV_OFF0 + 4 * AV_STAGE)
#define NKT       (N_ / 32)

__device__ __forceinline__ void av_load_stage(uint32_t sbase,
                                              const char* gV, const char* gP,
                                              int kt, int tid) {
    const size_t gcol = (size_t)kt * 64;
#pragma unroll
    for (int i = 0; i < 4; i++) {
        int id  = tid + i * 128;
        int row = id >> 2, ch = id & 3;
        int phys = ch ^ ((row >> 1) & 3);
        uint32_t so = row * 64 + phys * 16;
        size_t   go = (size_t)row * (N_ * 2) + gcol + ch * 16;
        cp16(sbase + so,        gV + go);
        cp16(sbase + 8192 + so, gP + go);
    }
}

__global__ __launch_bounds__(128, 2)
void av_gemm_kernel(const float* __restrict__ x, float* __restrict__ out) {
    extern __shared__ char dsm[];
    const uint32_t sb = smem_u32(dsm);
    const int tid  = threadIdx.x;
    const int wid  = tid >> 5;
    const int lane = tid & 31;
    const int wr   = wid & 1;     // c half (64 of 128)
    const int wc   = wid >> 1;    // n half (64 of 128)
    const int n0 = blockIdx.x * 128;
    const int c0 = blockIdx.y * 128;
    const int b  = blockIdx.z;

    float* sm_inv = (float*)dsm;
    sm_inv[tid] = 1.0f / g_L[b * N_ + n0 + tid];

    const char* gV = (const char*)g_Vf + ((size_t)(b * C_ + c0)) * N_ * 2;
    const char* gP = (const char*)g_P  + ((size_t)b * N_ + n0) * N_ * 2;

    uint32_t rowA[4], swzA[4];
#pragma unroll
    for (int mt = 0; mt < 4; mt++) {
        rowA[mt] = wr * 64 + mt * 16 + (lane & 15);
        swzA[mt] = (rowA[mt] >> 1) & 3;
    }
    const uint32_t khA = lane >> 4;
    uint32_t rowB[4], swzB[4];
#pragma unroll
    for (int nt2 = 0; nt2 < 4; nt2++) {
        rowB[nt2] = wc * 64 + nt2 * 16 + (lane & 7) + ((lane >> 4) << 3);
        swzB[nt2] = (rowB[nt2] >> 1) & 3;
    }
    const uint32_t khB = (lane >> 3) & 1;

    float acc[4][8][4];
#pragma unroll
    for (int mt = 0; mt < 4; mt++)
#pragma unroll
        for (int nt = 0; nt < 8; nt++)
#pragma unroll
            for (int r = 0; r < 4; r++) acc[mt][nt][r] = 0.f;

    av_load_stage(sb + AV_OFF0,                gV, gP, 0, tid); cp_commit();
    av_load_stage(sb + AV_OFF0 +     AV_STAGE, gV, gP, 1, tid); cp_commit();
    av_load_stage(sb + AV_OFF0 + 2 * AV_STAGE, gV, gP, 2, tid); cp_commit();

    for (int kt = 0; kt < NKT; kt++) {
        cp_wait2();            // stage kt landed
        __syncthreads();       // all warps finished stage kt-1's buffer
        if (kt + 3 < NKT)
            av_load_stage(sb + AV_OFF0 + ((kt + 3) & 3) * AV_STAGE, gV, gP, kt + 3, tid);
        cp_commit();           // unconditional: uniform group counting

        const uint32_t buf = sb + AV_OFF0 + (kt & 3) * AV_STAGE;
#pragma unroll
        for (int ks = 0; ks < 2; ks++) {
            uint32_t bb[4][4];
#pragma unroll
            for (int nt2 = 0; nt2 < 4; nt2++) {
                uint32_t ch = ((ks * 2 + khB) ^ swzB[nt2]) * 16;
                ldm_x4(bb[nt2], buf + 8192 + rowB[nt2] * 64 + ch);
            }
            uint32_t aa[4][4];
#pragma unroll
            for (int mt = 0; mt < 4; mt++) {
                uint32_t ch = ((ks * 2 + khA) ^ swzA[mt]) * 16;
                ldm_x4(aa[mt], buf + rowA[mt] * 64 + ch);
            }
#pragma unroll
            for (int mt = 0; mt < 4; mt++)
#pragma unroll
                for (int nt = 0; nt < 8; nt++)
                    mma16816h(acc[mt][nt], aa[mt], &bb[nt >> 1][(nt & 1) * 2]);
        }
    }

    // Epilogue: scale by 1/L, add residual, store fp32.
#pragma unroll
    for (int mt = 0; mt < 4; mt++) {
        int cA = c0 + wr * 64 + mt * 16 + (lane >> 2);
#pragma unroll
        for (int nt = 0; nt < 8; nt++) {
            int nl = wc * 64 + nt * 8 + (lane & 3) * 2;
            float i0 = sm_inv[nl], i1 = sm_inv[nl + 1];
            size_t o0 = ((size_t)(b * C_ + cA)) * N_ + n0 + nl;
            float2 xv = *(const float2*)(x + o0);
            float2 ov;
            ov.x = acc[mt][nt][0] * i0 + xv.x;
            ov.y = acc[mt][nt][1] * i1 + xv.y;
            *(float2*)(out + o0) = ov;
            size_t o1 = o0 + (size_t)8 * N_;
            float2 xv2 = *(const float2*)(x + o1);
            float2 ov2;
            ov2.x = acc[mt][nt][2] * i0 + xv2.x;
            ov2.y = acc[mt][nt][3] * i1 + xv2.y;
            *(float2*)(out + o1) = ov2;
        }
    }
}

// ---------------------------------------------------------------------------
extern "C" void kernel_launch(void* const* d_in, const int* in_sizes, int n_in,
                              void* d_out, int out_size) {
    const float* x  = (const float*)d_in[0];
    const float* Wq = (const float*)d_in[1];
    const float* bq = (const float*)d_in[2];
    const float* Wk = (const float*)d_in[3];
    const float* bk = (const float*)d_in[4];
    const float* Wv = (const float*)d_in[5];
    const float* bv = (const float*)d_in[6];
    float* out = (float*)d_out;

    const int qk_smem = 2 * D_ * C_ * (int)sizeof(float);  // 64 KB

    cudaFuncSetAttribute(qk_proj_kernel,  cudaFuncAttributeMaxDynamicSharedMemorySize, qk_smem);
    cudaFuncSetAttribute(scores_p_kernel, cudaFuncAttributeMaxDynamicSharedMemorySize, S_TOTAL);
    cudaFuncSetAttribute(av_gemm_kernel,  cudaFuncAttributeMaxDynamicSharedMemorySize, AV_TOTAL);

    qk_proj_kernel<<<dim3(N_ / 64, B_), 256, qk_smem>>>(x, Wq, bq, Wk, bk);
    v_proj_kernel<<<dim3(N_ / 64, C_ / 64, B_), 256>>>(x, Wv, bv);
    scores_p_kernel<<<dim3(N_ / 64, B_), 256, S_TOTAL>>>();
    av_gemm_kernel<<<dim3(N_ / 128, C_ / 128, B_), 128, AV_TOTAL>>>(x, out);
}

// round 15
// speedup vs baseline: 1.5098x; 1.0006x over previous
#include <cuda_runtime.h>
#include <cuda_fp16.h>
#include <cstdint>

#define B_ 8
#define C_ 256
#define D_ 32
#define N_ 4096

#define SHIFT_ 16.0f

// ---------------------------------------------------------------------------
// Scratch (allocation-free rule: __device__ globals)
// ---------------------------------------------------------------------------
__device__ __half  g_x16[(size_t)B_ * N_ * C_];   // [b][n][c] fp16 (transposed x)
__device__ __half  g_W16[320 * C_];               // rows: 0-31 Wq, 32-63 Wk, 64-319 Wv
__device__ float   g_bias[320];                   // bq | bk | bv
__device__ __half  g_Qf[(size_t)B_ * N_ * D_];    // [b][n][d] fp16
__device__ __half  g_Kf[(size_t)B_ * N_ * D_];    // [b][m][d] fp16
__device__ __half  g_Vf[(size_t)B_ * C_ * N_];    // [b][c][m] fp16
__device__ __half  g_P[(size_t)B_ * N_ * N_];     // [b][n][m] exp(s-16) fp16
__device__ float   g_L[B_ * N_];                  // row sum of quantized p

// ---------------------------------------------------------------------------
// Portable PTX helpers
// ---------------------------------------------------------------------------
__device__ __forceinline__ uint32_t smem_u32(const void* p) {
    uint32_t a;
    asm("{ .reg .u64 t; cvta.to.shared.u64 t, %1; cvt.u32.u64 %0, t; }" : "=r"(a) : "l"(p));
    return a;
}
__device__ __forceinline__ void cp16(uint32_t s, const void* g) {
    asm volatile("cp.async.cg.shared.global [%0], [%1], 16;" :: "r"(s), "l"(g));
}
__device__ __forceinline__ void cp_commit() {
    asm volatile("cp.async.commit_group;" ::: "memory");
}
__device__ __forceinline__ void cp_wait0() {
    asm volatile("cp.async.wait_group 0;" ::: "memory");
}
__device__ __forceinline__ void cp_wait1() {
    asm volatile("cp.async.wait_group 1;" ::: "memory");
}
__device__ __forceinline__ void cp_wait2() {
    asm volatile("cp.async.wait_group 2;" ::: "memory");
}
__device__ __forceinline__ void ldm_x4(uint32_t* r, uint32_t addr) {
    asm volatile("ldmatrix.sync.aligned.m8n8.x4.shared.b16 {%0,%1,%2,%3}, [%4];"
                 : "=r"(r[0]), "=r"(r[1]), "=r"(r[2]), "=r"(r[3]) : "r"(addr));
}
__device__ __forceinline__ void mma16816h(float* d, const uint32_t* a, const uint32_t* b) {
    asm volatile(
        "mma.sync.aligned.m16n8k16.row.col.f32.f16.f16.f32 "
        "{%0,%1,%2,%3}, {%4,%5,%6,%7}, {%8,%9}, {%0,%1,%2,%3};"
        : "+f"(d[0]), "+f"(d[1]), "+f"(d[2]), "+f"(d[3])
        : "r"(a[0]), "r"(a[1]), "r"(a[2]), "r"(a[3]), "r"(b[0]), "r"(b[1]));
}

// ---------------------------------------------------------------------------
// Kernel 0a: W / bias -> fp16 stacked [320][256].
// ---------------------------------------------------------------------------
__global__ __launch_bounds__(256)
void wconv_kernel(const float* __restrict__ Wq, const float* __restrict__ bq,
                  const float* __restrict__ Wk, const float* __restrict__ bk,
                  const float* __restrict__ Wv, const float* __restrict__ bv) {
    int idx = blockIdx.x * 256 + threadIdx.x;      // 0 .. 81919
    int row = idx >> 8, col = idx & 255;
    float w = (row < 32) ? Wq[row * C_ + col]
            : (row < 64) ? Wk[(row - 32) * C_ + col]
                         : Wv[(row - 64) * C_ + col];
    g_W16[idx] = __float2half_rn(w);
    if (idx < 320) {
        g_bias[idx] = (idx < 32) ? bq[idx] : (idx < 64) ? bk[idx - 32] : bv[idx - 64];
    }
}

// ---------------------------------------------------------------------------
// Kernel 0b: x [b][c][n] fp32 -> g_x16 [b][n][c] fp16 (32x32 tile transpose).
// ---------------------------------------------------------------------------
__global__ __launch_bounds__(256)
void xconv_kernel(const float* __restrict__ x) {
    __shared__ float t[32][33];
    const int b = blockIdx.z, c0 = blockIdx.y * 32, n0 = blockIdx.x * 32;
    const int tid = threadIdx.x;
    {
        int cl = tid >> 3, nf = (tid & 7) * 4;
        float4 v = *(const float4*)(x + ((size_t)(b * C_ + c0 + cl)) * N_ + n0 + nf);
        t[cl][nf + 0] = v.x; t[cl][nf + 1] = v.y;
        t[cl][nf + 2] = v.z; t[cl][nf + 3] = v.w;
    }
    __syncthreads();
    {
        int nl = tid >> 3, cf = (tid & 7) * 4;
        __half h4[4];
#pragma unroll
        for (int i = 0; i < 4; i++) h4[i] = __float2half_rn(t[cf + i][nl]);
        *(uint2*)(g_x16 + ((size_t)(b * N_ + n0 + nl)) * C_ + c0 + cf) = *(uint2*)h4;
    }
}

// ---------------------------------------------------------------------------
// Kernel 1: QKV projection GEMM (HMMA fp16).
//   out[e][n] = sum_c W16[e][c] * x16[n][c] + bias[e],  e in [0,320)
// CTA: 64e x 128n, 256 thr / 8 warps (2e x 4n), warp tile 32x32.
// K=256, chunks of 32, 2-stage cp.async. blockIdx.y==0 -> Q/K (transposed
// store via smem); y>=1 -> V rows (direct [c][n] store).
// ---------------------------------------------------------------------------
#define GO_A    512
#define GO_B    (GO_A + 2 * 4096)
#define G_TOTAL (GO_B + 2 * 8192)

__global__ __launch_bounds__(256, 2)
void qkv_gemm_kernel() {
    extern __shared__ char gsm[];
    const uint32_t sb = smem_u32(gsm);
    const int b   = blockIdx.z;
    const int n0  = blockIdx.x * 128;
    const int e0  = blockIdx.y * 64;
    const int tid = threadIdx.x;
    const int lane = tid & 31;
    const int wm  = (tid >> 5) & 1;     // e half (32)
    const int wn  = tid >> 6;           // n quarter (32)

    const char* gA = (const char*)g_W16 + (size_t)e0 * C_ * 2;
    const char* gB = (const char*)g_x16 + ((size_t)b * N_ + n0) * C_ * 2;

    // stage loaders (A: 64 rows x 64B; B: 128 rows x 64B; 64B-row swizzle)
    auto load_a = [&](uint32_t sbase, int kt) {
        int row = tid >> 2, ch = tid & 3;
        int phys = ch ^ ((row >> 1) & 3);
        cp16(sbase + row * 64 + phys * 16, gA + (size_t)row * 512 + kt * 64 + ch * 16);
    };
    auto load_b = [&](uint32_t sbase, int kt) {
#pragma unroll
        for (int i = 0; i < 2; i++) {
            int id = tid + i * 256;
            int row = id >> 2, ch = id & 3;
            int phys = ch ^ ((row >> 1) & 3);
            cp16(sbase + row * 64 + phys * 16, gB + (size_t)row * 512 + kt * 64 + ch * 16);
        }
    };

    load_a(sb + GO_A, 0);
    load_b(sb + GO_B, 0);
    cp_commit();

    float acc[2][4][4];
#pragma unroll
    for (int mt = 0; mt < 2; mt++)
#pragma unroll
        for (int nt = 0; nt < 4; nt++)
#pragma unroll
            for (int r = 0; r < 4; r++) acc[mt][nt][r] = 0.f;

    for (int kt = 0; kt < 8; kt++) {
        if (kt + 1 < 8) {
            load_a(sb + GO_A + ((kt + 1) & 1) * 4096, kt + 1);
            load_b(sb + GO_B + ((kt + 1) & 1) * 8192, kt + 1);
            cp_commit();
            cp_wait1();
        } else {
            cp_wait0();
        }
        __syncthreads();

        const uint32_t abase = sb + GO_A + (kt & 1) * 4096;
        const uint32_t bbase = sb + GO_B + (kt & 1) * 8192;
#pragma unroll
        for (int ks = 0; ks < 2; ks++) {
            uint32_t af[2][4];
#pragma unroll
            for (int mt = 0; mt < 2; mt++) {
                uint32_t row = wm * 32 + mt * 16 + (lane & 15);
                uint32_t chl = ks * 2 + (lane >> 4);
                uint32_t phys = chl ^ ((row >> 1) & 3);
                ldm_x4(af[mt], abase + row * 64 + phys * 16);
            }
            uint32_t bf[2][4];
#pragma unroll
            for (int nt2 = 0; nt2 < 2; nt2++) {
                uint32_t row = wn * 32 + nt2 * 16 + (lane & 7) + ((lane >> 4) << 3);
                uint32_t chl = ks * 2 + ((lane >> 3) & 1);
                uint32_t phys = chl ^ ((row >> 1) & 3);
                ldm_x4(bf[nt2], bbase + row * 64 + phys * 16);
            }
#pragma unroll
            for (int mt = 0; mt < 2; mt++)
#pragma unroll
                for (int nt = 0; nt < 4; nt++)
                    mma16816h(acc[mt][nt], af[mt], &bf[nt >> 1][(nt & 1) * 2]);
        }
        __syncthreads();
    }

    if (e0 >= 64) {
        // V rows: direct store to g_Vf [c][n], c = e - 64.
#pragma unroll
        for (int mt = 0; mt < 2; mt++) {
#pragma unroll
            for (int half_ = 0; half_ < 2; half_++) {
                int eloc = wm * 32 + mt * 16 + (lane >> 2) + half_ * 8;
                float bias = g_bias[e0 + eloc];
                int c = e0 - 64 + eloc;
                __half* dst = g_Vf + ((size_t)(b * C_ + c)) * N_ + n0;
#pragma unroll
                for (int nt = 0; nt < 4; nt++) {
                    int nl = wn * 32 + nt * 8 + (lane & 3) * 2;
                    __half2 h = __floats2half2_rn(acc[mt][nt][half_ * 2 + 0] + bias,
                                                  acc[mt][nt][half_ * 2 + 1] + bias);
                    *(__half2*)(dst + nl) = h;
                }
            }
        }
    } else {
        // Q/K rows: stage [64e][128n] fp16 tile in smem, then transposed store.
        __half* smt = (__half*)(gsm + GO_A);     // [64][132]
#pragma unroll
        for (int mt = 0; mt < 2; mt++) {
#pragma unroll
            for (int half_ = 0; half_ < 2; half_++) {
                int eloc = wm * 32 + mt * 16 + (lane >> 2) + half_ * 8;
                float bias = g_bias[e0 + eloc];
#pragma unroll
                for (int nt = 0; nt < 4; nt++) {
                    int nl = wn * 32 + nt * 8 + (lane & 3) * 2;
                    smt[eloc * 132 + nl]     = __float2half_rn(acc[mt][nt][half_ * 2 + 0] + bias);
                    smt[eloc * 132 + nl + 1] = __float2half_rn(acc[mt][nt][half_ * 2 + 1] + bias);
                }
            }
        }
        __syncthreads();
        const int n = tid >> 1;          // 0..127
        const int h = tid & 1;           // 0 = Q, 1 = K
        __half row16[32];
#pragma unroll
        for (int d = 0; d < 32; d++) row16[d] = smt[(h * 32 + d) * 132 + n];
        __half* dst = (h == 0 ? g_Qf : g_Kf) + ((size_t)(b * N_ + n0 + n)) * 32;
        *(uint4*)(dst)     = *(uint4*)(row16);
        *(uint4*)(dst + 8) = *(uint4*)(row16 + 8);
        *(uint4*)(dst + 16) = *(uint4*)(row16 + 16);
        *(uint4*)(dst + 24) = *(uint4*)(row16 + 24);
    }
}

// ---------------------------------------------------------------------------
// Kernel 2: HMMA fp16 scores + shifted exp + quantize + L.  (unchanged)
// ---------------------------------------------------------------------------
#define S_NIT   (N_ / 128)
#define SO_Q    512
#define SO_K    (SO_Q + 4096)
#define S_TOTAL (SO_K + 2 * 8192)

__device__ __forceinline__ void s_load_k(uint32_t sbase, int b, int m0, int tid) {
    const char* gk = (const char*)g_Kf + ((size_t)b * N_ + m0) * 64;
#pragma unroll
    for (int i = 0; i < 2; i++) {
        int id = tid + i * 256;
        int row = id >> 2, ch = id & 3;
        int phys = ch ^ ((row >> 1) & 3);
        cp16(sbase + row * 64 + phys * 16, gk + row * 64 + ch * 16);
    }
}

__global__ __launch_bounds__(256, 3)
void scores_p_kernel() {
    extern __shared__ char ssm[];
    const uint32_t sb = smem_u32(ssm);
    float* smL = (float*)ssm;
    const int b    = blockIdx.y;
    const int n0   = blockIdx.x * 64;
    const int tid  = threadIdx.x;
    const int lane = tid & 31;
    const int wn   = (tid >> 5) & 1;
    const int wm   = tid >> 6;

    if (tid < 64) smL[tid] = 0.f;

    {
        int row = tid >> 2, ch = tid & 3;
        int phys = ch ^ ((row >> 1) & 3);
        const char* gq = (const char*)g_Qf + ((size_t)b * N_ + n0) * 64;
        cp16(sb + SO_Q + row * 64 + phys * 16, gq + row * 64 + ch * 16);
    }
    s_load_k(sb + SO_K, b, 0, tid);
    cp_commit();
    cp_wait0();
    __syncthreads();

    uint32_t aq[2][2][4];
#pragma unroll
    for (int mt = 0; mt < 2; mt++)
#pragma unroll
        for (int kk = 0; kk < 2; kk++) {
            uint32_t row = wn * 32 + mt * 16 + (lane & 15);
            uint32_t chl = 2 * kk + (lane >> 4);
            uint32_t phys = chl ^ ((row >> 1) & 3);
            ldm_x4(aq[mt][kk], sb + SO_Q + row * 64 + phys * 16);
        }

    float Lp[4] = {0.f, 0.f, 0.f, 0.f};

    for (int kt = 0; kt < S_NIT; kt++) {
        if (kt + 1 < S_NIT) {
            s_load_k(sb + SO_K + ((kt + 1) & 1) * 8192, b, (kt + 1) * 128, tid);
            cp_commit();
            cp_wait1();
        } else {
            cp_wait0();
        }
        __syncthreads();

        const uint32_t kbase = sb + SO_K + (kt & 1) * 8192;
        float acc[2][4][4];
#pragma unroll
        for (int mt = 0; mt < 2; mt++)
#pragma unroll
            for (int nt = 0; nt < 4; nt++)
#pragma unroll
                for (int r = 0; r < 4; r++) acc[mt][nt][r] = 0.f;

#pragma unroll
        for (int kk = 0; kk < 2; kk++) {
            uint32_t kf[2][4];
#pragma unroll
            for (int nt2 = 0; nt2 < 2; nt2++) {
                uint32_t row = wm * 32 + nt2 * 16 + (lane & 7) + ((lane >> 4) << 3);
                uint32_t chl = 2 * kk + ((lane >> 3) & 1);
                uint32_t phys = chl ^ ((row >> 1) & 3);
                ldm_x4(kf[nt2], kbase + row * 64 + phys * 16);
            }
#pragma unroll
            for (int mt = 0; mt < 2; mt++)
#pragma unroll
                for (int nt = 0; nt < 4; nt++)
                    mma16816h(acc[mt][nt], aq[mt][kk], &kf[nt >> 1][(nt & 1) * 2]);
        }

        const int m0 = kt * 128;
#pragma unroll
        for (int mt = 0; mt < 2; mt++) {
            const int r0 = n0 + wn * 32 + mt * 16 + (lane >> 2);
            const size_t rb0 = ((size_t)b * N_ + r0) * N_;
            const size_t rb1 = rb0 + (size_t)8 * N_;
#pragma unroll
            for (int nt = 0; nt < 4; nt++) {
                const int mc = m0 + wm * 32 + nt * 8 + (lane & 3) * 2;
                float e0 = __expf(acc[mt][nt][0] - SHIFT_);
                float e1 = __expf(acc[mt][nt][1] - SHIFT_);
                float e2 = __expf(acc[mt][nt][2] - SHIFT_);
                float e3 = __expf(acc[mt][nt][3] - SHIFT_);
                __half2 p01 = __floats2half2_rn(e0, e1);
                __half2 p23 = __floats2half2_rn(e2, e3);
                Lp[mt * 2 + 0] += __low2float(p01) + __high2float(p01);
                Lp[mt * 2 + 1] += __low2float(p23) + __high2float(p23);
                *(uint32_t*)(g_P + rb0 + mc) = *(uint32_t*)&p01;
                *(uint32_t*)(g_P + rb1 + mc) = *(uint32_t*)&p23;
            }
        }
        __syncthreads();
    }

#pragma unroll
    for (int i = 0; i < 4; i++) {
        Lp[i] += __shfl_xor_sync(0xffffffffu, Lp[i], 1);
        Lp[i] += __shfl_xor_sync(0xffffffffu, Lp[i], 2);
    }
    if ((lane & 3) == 0) {
        int rbase = wn * 32 + (lane >> 2);
        atomicAdd(&smL[rbase + 0],  Lp[0]);
        atomicAdd(&smL[rbase + 8],  Lp[1]);
        atomicAdd(&smL[rbase + 16], Lp[2]);
        atomicAdd(&smL[rbase + 24], Lp[3]);
    }
    __syncthreads();
    if (tid < 64) g_L[b * N_ + n0 + tid] = smL[tid];
}

// ---------------------------------------------------------------------------
// Kernel 3: AV GEMM fp16, CTA 128x128 with 128 thr / 4 warps (2c x 2n),
// warp tile 64x64. 4-stage cp.async.  (unchanged from R12)
// ---------------------------------------------------------------------------
#define AV_OFF0   1024
#define AV_STAGE  16384
#define AV_TOTAL  (AV_OFF0 + 4 * AV_STAGE)
#define NKT       (N_ / 32)

__device__ __forceinline__ void av_load_stage(uint32_t sbase,
                                              const char* gV, const char* gP,
                                              int kt, int tid) {
    const size_t gcol = (size_t)kt * 64;
#pragma unroll
    for (int i = 0; i < 4; i++) {
        int id  = tid + i * 128;
        int row = id >> 2, ch = id & 3;
        int phys = ch ^ ((row >> 1) & 3);
        uint32_t so = row * 64 + phys * 16;
        size_t   go = (size_t)row * (N_ * 2) + gcol + ch * 16;
        cp16(sbase + so,        gV + go);
        cp16(sbase + 8192 + so, gP + go);
    }
}

__global__ __launch_bounds__(128, 2)
void av_gemm_kernel(const float* __restrict__ x, float* __restrict__ out) {
    extern __shared__ char dsm[];
    const uint32_t sb = smem_u32(dsm);
    const int tid  = threadIdx.x;
    const int wid  = tid >> 5;
    const int lane = tid & 31;
    const int wr   = wid & 1;
    const int wc   = wid >> 1;
    const int n0 = blockIdx.x * 128;
    const int c0 = blockIdx.y * 128;
    const int b  = blockIdx.z;

    float* sm_inv = (float*)dsm;
    sm_inv[tid] = 1.0f / g_L[b * N_ + n0 + tid];

    const char* gV = (const char*)g_Vf + ((size_t)(b * C_ + c0)) * N_ * 2;
    const char* gP = (const char*)g_P  + ((size_t)b * N_ + n0) * N_ * 2;

    uint32_t rowA[4], swzA[4];
#pragma unroll
    for (int mt = 0; mt < 4; mt++) {
        rowA[mt] = wr * 64 + mt * 16 + (lane & 15);
        swzA[mt] = (rowA[mt] >> 1) & 3;
    }
    const uint32_t khA = lane >> 4;
    uint32_t rowB[4], swzB[4];
#pragma unroll
    for (int nt2 = 0; nt2 < 4; nt2++) {
        rowB[nt2] = wc * 64 + nt2 * 16 + (lane & 7) + ((lane >> 4) << 3);
        swzB[nt2] = (rowB[nt2] >> 1) & 3;
    }
    const uint32_t khB = (lane >> 3) & 1;

    float acc[4][8][4];
#pragma unroll
    for (int mt = 0; mt < 4; mt++)
#pragma unroll
        for (int nt = 0; nt < 8; nt++)
#pragma unroll
            for (int r = 0; r < 4; r++) acc[mt][nt][r] = 0.f;

    av_load_stage(sb + AV_OFF0,                gV, gP, 0, tid); cp_commit();
    av_load_stage(sb + AV_OFF0 +     AV_STAGE, gV, gP, 1, tid); cp_commit();
    av_load_stage(sb + AV_OFF0 + 2 * AV_STAGE, gV, gP, 2, tid); cp_commit();

    for (int kt = 0; kt < NKT; kt++) {
        cp_wait2();
        __syncthreads();
        if (kt + 3 < NKT)
            av_load_stage(sb + AV_OFF0 + ((kt + 3) & 3) * AV_STAGE, gV, gP, kt + 3, tid);
        cp_commit();

        const uint32_t buf = sb + AV_OFF0 + (kt & 3) * AV_STAGE;
#pragma unroll
        for (int ks = 0; ks < 2; ks++) {
            uint32_t bb[4][4];
#pragma unroll
            for (int nt2 = 0; nt2 < 4; nt2++) {
                uint32_t ch = ((ks * 2 + khB) ^ swzB[nt2]) * 16;
                ldm_x4(bb[nt2], buf + 8192 + rowB[nt2] * 64 + ch);
            }
            uint32_t aa[4][4];
#pragma unroll
            for (int mt = 0; mt < 4; mt++) {
                uint32_t ch = ((ks * 2 + khA) ^ swzA[mt]) * 16;
                ldm_x4(aa[mt], buf + rowA[mt] * 64 + ch);
            }
#pragma unroll
            for (int mt = 0; mt < 4; mt++)
#pragma unroll
                for (int nt = 0; nt < 8; nt++)
                    mma16816h(acc[mt][nt], aa[mt], &bb[nt >> 1][(nt & 1) * 2]);
        }
    }

#pragma unroll
    for (int mt = 0; mt < 4; mt++) {
        int cA = c0 + wr * 64 + mt * 16 + (lane >> 2);
#pragma unroll
        for (int nt = 0; nt < 8; nt++) {
            int nl = wc * 64 + nt * 8 + (lane & 3) * 2;
            float i0 = sm_inv[nl], i1 = sm_inv[nl + 1];
            size_t o0 = ((size_t)(b * C_ + cA)) * N_ + n0 + nl;
            float2 xv = *(const float2*)(x + o0);
            float2 ov;
            ov.x = acc[mt][nt][0] * i0 + xv.x;
            ov.y = acc[mt][nt][1] * i1 + xv.y;
            *(float2*)(out + o0) = ov;
            size_t o1 = o0 + (size_t)8 * N_;
            float2 xv2 = *(const float2*)(x + o1);
            float2 ov2;
            ov2.x = acc[mt][nt][2] * i0 + xv2.x;
            ov2.y = acc[mt][nt][3] * i1 + xv2.y;
            *(float2*)(out + o1) = ov2;
        }
    }
}

// ---------------------------------------------------------------------------
extern "C" void kernel_launch(void* const* d_in, const int* in_sizes, int n_in,
                              void* d_out, int out_size) {
    const float* x  = (const float*)d_in[0];
    const float* Wq = (const float*)d_in[1];
    const float* bq = (const float*)d_in[2];
    const float* Wk = (const float*)d_in[3];
    const float* bk = (const float*)d_in[4];
    const float* Wv = (const float*)d_in[5];
    const float* bv = (const float*)d_in[6];
    float* out = (float*)d_out;

    cudaFuncSetAttribute(qkv_gemm_kernel, cudaFuncAttributeMaxDynamicSharedMemorySize, G_TOTAL);
    cudaFuncSetAttribute(scores_p_kernel, cudaFuncAttributeMaxDynamicSharedMemorySize, S_TOTAL);
    cudaFuncSetAttribute(av_gemm_kernel,  cudaFuncAttributeMaxDynamicSharedMemorySize, AV_TOTAL);

    wconv_kernel<<<320, 256>>>(Wq, bq, Wk, bk, Wv, bv);
    xconv_kernel<<<dim3(N_ / 32, C_ / 32, B_), 256>>>(x);
    qkv_gemm_kernel<<<dim3(N_ / 128, 5, B_), 256, G_TOTAL>>>();
    scores_p_kernel<<<dim3(N_ / 64, B_), 256, S_TOTAL>>>();
    av_gemm_kernel<<<dim3(N_ / 128, C_ / 128, B_), 128, AV_TOTAL>>>(x, out);
}

// round 16
// speedup vs baseline: 2.4142x; 1.5990x over previous
#include <cuda_runtime.h>
#include <cuda_fp16.h>
#include <cstdint>

#define B_ 8
#define C_ 256
#define D_ 32
#define N_ 4096

#define SHIFT_ 16.0f

// ---------------------------------------------------------------------------
// Scratch (allocation-free rule: __device__ globals)
// ---------------------------------------------------------------------------
__device__ __half  g_x16[(size_t)B_ * N_ * C_];   // [b][n][c] fp16 (transposed x)
__device__ __half  g_W16[320 * C_];               // rows: 0-31 Wq, 32-63 Wk, 64-319 Wv
__device__ float   g_bias[320];                   // bq | bk | bv
__device__ __half  g_Qf[(size_t)B_ * N_ * D_];    // [b][n][d] fp16
__device__ __half  g_Kf[(size_t)B_ * N_ * D_];    // [b][m][d] fp16
__device__ __half  g_Vf[(size_t)B_ * C_ * N_];    // [b][c][m] fp16
__device__ __half  g_P[(size_t)B_ * N_ * N_];     // [b][n][m] exp(s-16) fp16
__device__ float   g_L[B_ * N_];                  // row sum of quantized p

// ---------------------------------------------------------------------------
// Portable PTX helpers
// ---------------------------------------------------------------------------
__device__ __forceinline__ uint32_t smem_u32(const void* p) {
    uint32_t a;
    asm("{ .reg .u64 t; cvta.to.shared.u64 t, %1; cvt.u32.u64 %0, t; }" : "=r"(a) : "l"(p));
    return a;
}
__device__ __forceinline__ void cp16(uint32_t s, const void* g) {
    asm volatile("cp.async.cg.shared.global [%0], [%1], 16;" :: "r"(s), "l"(g));
}
__device__ __forceinline__ void cp_commit() {
    asm volatile("cp.async.commit_group;" ::: "memory");
}
__device__ __forceinline__ void cp_wait0() {
    asm volatile("cp.async.wait_group 0;" ::: "memory");
}
__device__ __forceinline__ void cp_wait1() {
    asm volatile("cp.async.wait_group 1;" ::: "memory");
}
__device__ __forceinline__ void cp_wait2() {
    asm volatile("cp.async.wait_group 2;" ::: "memory");
}
__device__ __forceinline__ void ldm_x4(uint32_t* r, uint32_t addr) {
    asm volatile("ldmatrix.sync.aligned.m8n8.x4.shared.b16 {%0,%1,%2,%3}, [%4];"
                 : "=r"(r[0]), "=r"(r[1]), "=r"(r[2]), "=r"(r[3]) : "r"(addr));
}
__device__ __forceinline__ void mma16816h(float* d, const uint32_t* a, const uint32_t* b) {
    asm volatile(
        "mma.sync.aligned.m16n8k16.row.col.f32.f16.f16.f32 "
        "{%0,%1,%2,%3}, {%4,%5,%6,%7}, {%8,%9}, {%0,%1,%2,%3};"
        : "+f"(d[0]), "+f"(d[1]), "+f"(d[2]), "+f"(d[3])
        : "r"(a[0]), "r"(a[1]), "r"(a[2]), "r"(a[3]), "r"(b[0]), "r"(b[1]));
}

// ---------------------------------------------------------------------------
// Kernel 0a: W / bias -> fp16 stacked [320][256].
// ---------------------------------------------------------------------------
__global__ __launch_bounds__(256)
void wconv_kernel(const float* __restrict__ Wq, const float* __restrict__ bq,
                  const float* __restrict__ Wk, const float* __restrict__ bk,
                  const float* __restrict__ Wv, const float* __restrict__ bv) {
    int idx = blockIdx.x * 256 + threadIdx.x;      // 0 .. 81919
    int row = idx >> 8, col = idx & 255;
    float w = (row < 32) ? Wq[row * C_ + col]
            : (row < 64) ? Wk[(row - 32) * C_ + col]
                         : Wv[(row - 64) * C_ + col];
    g_W16[idx] = __float2half_rn(w);
    if (idx < 320) {
        g_bias[idx] = (idx < 32) ? bq[idx] : (idx < 64) ? bk[idx - 32] : bv[idx - 64];
    }
}

// ---------------------------------------------------------------------------
// Kernel 0b: x [b][c][n] fp32 -> g_x16 [b][n][c] fp16 (32x32 tile transpose).
// ---------------------------------------------------------------------------
__global__ __launch_bounds__(256)
void xconv_kernel(const float* __restrict__ x) {
    __shared__ float t[32][33];
    const int b = blockIdx.z, c0 = blockIdx.y * 32, n0 = blockIdx.x * 32;
    const int tid = threadIdx.x;
    {
        int cl = tid >> 3, nf = (tid & 7) * 4;
        float4 v = *(const float4*)(x + ((size_t)(b * C_ + c0 + cl)) * N_ + n0 + nf);
        t[cl][nf + 0] = v.x; t[cl][nf + 1] = v.y;
        t[cl][nf + 2] = v.z; t[cl][nf + 3] = v.w;
    }
    __syncthreads();
    {
        int nl = tid >> 3, cf = (tid & 7) * 4;
        __half h4[4];
#pragma unroll
        for (int i = 0; i < 4; i++) h4[i] = __float2half_rn(t[cf + i][nl]);
        *(uint2*)(g_x16 + ((size_t)(b * N_ + n0 + nl)) * C_ + c0 + cf) = *(uint2*)h4;
    }
}

// ---------------------------------------------------------------------------
// Kernel 1: QKV projection GEMM (HMMA fp16).  (unchanged from R13)
// ---------------------------------------------------------------------------
#define GO_A    512
#define GO_B    (GO_A + 2 * 4096)
#define G_TOTAL (GO_B + 2 * 8192)

__global__ __launch_bounds__(256, 2)
void qkv_gemm_kernel() {
    extern __shared__ char gsm[];
    const uint32_t sb = smem_u32(gsm);
    const int b   = blockIdx.z;
    const int n0  = blockIdx.x * 128;
    const int e0  = blockIdx.y * 64;
    const int tid = threadIdx.x;
    const int lane = tid & 31;
    const int wm  = (tid >> 5) & 1;     // e half (32)
    const int wn  = tid >> 6;           // n quarter (32)

    const char* gA = (const char*)g_W16 + (size_t)e0 * C_ * 2;
    const char* gB = (const char*)g_x16 + ((size_t)b * N_ + n0) * C_ * 2;

    auto load_a = [&](uint32_t sbase, int kt) {
        int row = tid >> 2, ch = tid & 3;
        int phys = ch ^ ((row >> 1) & 3);
        cp16(sbase + row * 64 + phys * 16, gA + (size_t)row * 512 + kt * 64 + ch * 16);
    };
    auto load_b = [&](uint32_t sbase, int kt) {
#pragma unroll
        for (int i = 0; i < 2; i++) {
            int id = tid + i * 256;
            int row = id >> 2, ch = id & 3;
            int phys = ch ^ ((row >> 1) & 3);
            cp16(sbase + row * 64 + phys * 16, gB + (size_t)row * 512 + kt * 64 + ch * 16);
        }
    };

    load_a(sb + GO_A, 0);
    load_b(sb + GO_B, 0);
    cp_commit();

    float acc[2][4][4];
#pragma unroll
    for (int mt = 0; mt < 2; mt++)
#pragma unroll
        for (int nt = 0; nt < 4; nt++)
#pragma unroll
            for (int r = 0; r < 4; r++) acc[mt][nt][r] = 0.f;

    for (int kt = 0; kt < 8; kt++) {
        if (kt + 1 < 8) {
            load_a(sb + GO_A + ((kt + 1) & 1) * 4096, kt + 1);
            load_b(sb + GO_B + ((kt + 1) & 1) * 8192, kt + 1);
            cp_commit();
            cp_wait1();
        } else {
            cp_wait0();
        }
        __syncthreads();

        const uint32_t abase = sb + GO_A + (kt & 1) * 4096;
        const uint32_t bbase = sb + GO_B + (kt & 1) * 8192;
#pragma unroll
        for (int ks = 0; ks < 2; ks++) {
            uint32_t af[2][4];
#pragma unroll
            for (int mt = 0; mt < 2; mt++) {
                uint32_t row = wm * 32 + mt * 16 + (lane & 15);
                uint32_t chl = ks * 2 + (lane >> 4);
                uint32_t phys = chl ^ ((row >> 1) & 3);
                ldm_x4(af[mt], abase + row * 64 + phys * 16);
            }
            uint32_t bf[2][4];
#pragma unroll
            for (int nt2 = 0; nt2 < 2; nt2++) {
                uint32_t row = wn * 32 + nt2 * 16 + (lane & 7) + ((lane >> 4) << 3);
                uint32_t chl = ks * 2 + ((lane >> 3) & 1);
                uint32_t phys = chl ^ ((row >> 1) & 3);
                ldm_x4(bf[nt2], bbase + row * 64 + phys * 16);
            }
#pragma unroll
            for (int mt = 0; mt < 2; mt++)
#pragma unroll
                for (int nt = 0; nt < 4; nt++)
                    mma16816h(acc[mt][nt], af[mt], &bf[nt >> 1][(nt & 1) * 2]);
        }
        __syncthreads();
    }

    if (e0 >= 64) {
#pragma unroll
        for (int mt = 0; mt < 2; mt++) {
#pragma unroll
            for (int half_ = 0; half_ < 2; half_++) {
                int eloc = wm * 32 + mt * 16 + (lane >> 2) + half_ * 8;
                float bias = g_bias[e0 + eloc];
                int c = e0 - 64 + eloc;
                __half* dst = g_Vf + ((size_t)(b * C_ + c)) * N_ + n0;
#pragma unroll
                for (int nt = 0; nt < 4; nt++) {
                    int nl = wn * 32 + nt * 8 + (lane & 3) * 2;
                    __half2 h = __floats2half2_rn(acc[mt][nt][half_ * 2 + 0] + bias,
                                                  acc[mt][nt][half_ * 2 + 1] + bias);
                    *(__half2*)(dst + nl) = h;
                }
            }
        }
    } else {
        __half* smt = (__half*)(gsm + GO_A);     // [64][132]
#pragma unroll
        for (int mt = 0; mt < 2; mt++) {
#pragma unroll
            for (int half_ = 0; half_ < 2; half_++) {
                int eloc = wm * 32 + mt * 16 + (lane >> 2) + half_ * 8;
                float bias = g_bias[e0 + eloc];
#pragma unroll
                for (int nt = 0; nt < 4; nt++) {
                    int nl = wn * 32 + nt * 8 + (lane & 3) * 2;
                    smt[eloc * 132 + nl]     = __float2half_rn(acc[mt][nt][half_ * 2 + 0] + bias);
                    smt[eloc * 132 + nl + 1] = __float2half_rn(acc[mt][nt][half_ * 2 + 1] + bias);
                }
            }
        }
        __syncthreads();
        const int n = tid >> 1;          // 0..127
        const int h = tid & 1;           // 0 = Q, 1 = K
        __half row16[32];
#pragma unroll
        for (int d = 0; d < 32; d++) row16[d] = smt[(h * 32 + d) * 132 + n];
        __half* dst = (h == 0 ? g_Qf : g_Kf) + ((size_t)(b * N_ + n0 + n)) * 32;
        *(uint4*)(dst)     = *(uint4*)(row16);
        *(uint4*)(dst + 8) = *(uint4*)(row16 + 8);
        *(uint4*)(dst + 16) = *(uint4*)(row16 + 16);
        *(uint4*)(dst + 24) = *(uint4*)(row16 + 24);
    }
}

// ---------------------------------------------------------------------------
// Kernel 2: HMMA fp16 scores + shifted exp + quantize + L.
// NEW: P tile staged in padded smem (rows of 136 halves -> conflict-free
// half2 fragment stores), then cooperative LDS.128/STG.128 coalesced copy.
// ---------------------------------------------------------------------------
#define S_NIT   (N_ / 128)
#define SO_Q    512
#define SO_K    (SO_Q + 4096)
#define SO_T    (SO_K + 2 * 8192)            // 20992: P staging tile
#define S_TOTAL (SO_T + 64 * 136 * 2)        // + 17408 = 38400

__device__ __forceinline__ void s_load_k(uint32_t sbase, int b, int m0, int tid) {
    const char* gk = (const char*)g_Kf + ((size_t)b * N_ + m0) * 64;
#pragma unroll
    for (int i = 0; i < 2; i++) {
        int id = tid + i * 256;
        int row = id >> 2, ch = id & 3;
        int phys = ch ^ ((row >> 1) & 3);
        cp16(sbase + row * 64 + phys * 16, gk + row * 64 + ch * 16);
    }
}

__global__ __launch_bounds__(256, 3)
void scores_p_kernel() {
    extern __shared__ char ssm[];
    const uint32_t sb = smem_u32(ssm);
    float* smL = (float*)ssm;
    uint32_t* sPt = (uint32_t*)(ssm + SO_T);     // [64 rows][68 words]
    const int b    = blockIdx.y;
    const int n0   = blockIdx.x * 64;
    const int tid  = threadIdx.x;
    const int lane = tid & 31;
    const int wn   = (tid >> 5) & 1;
    const int wm   = tid >> 6;

    if (tid < 64) smL[tid] = 0.f;

    {
        int row = tid >> 2, ch = tid & 3;
        int phys = ch ^ ((row >> 1) & 3);
        const char* gq = (const char*)g_Qf + ((size_t)b * N_ + n0) * 64;
        cp16(sb + SO_Q + row * 64 + phys * 16, gq + row * 64 + ch * 16);
    }
    s_load_k(sb + SO_K, b, 0, tid);
    cp_commit();
    cp_wait0();
    __syncthreads();

    uint32_t aq[2][2][4];
#pragma unroll
    for (int mt = 0; mt < 2; mt++)
#pragma unroll
        for (int kk = 0; kk < 2; kk++) {
            uint32_t row = wn * 32 + mt * 16 + (lane & 15);
            uint32_t chl = 2 * kk + (lane >> 4);
            uint32_t phys = chl ^ ((row >> 1) & 3);
            ldm_x4(aq[mt][kk], sb + SO_Q + row * 64 + phys * 16);
        }

    float Lp[4] = {0.f, 0.f, 0.f, 0.f};

    for (int kt = 0; kt < S_NIT; kt++) {
        if (kt + 1 < S_NIT) {
            s_load_k(sb + SO_K + ((kt + 1) & 1) * 8192, b, (kt + 1) * 128, tid);
            cp_commit();
            cp_wait1();
        } else {
            cp_wait0();
        }
        __syncthreads();

        const uint32_t kbase = sb + SO_K + (kt & 1) * 8192;
        float acc[2][4][4];
#pragma unroll
        for (int mt = 0; mt < 2; mt++)
#pragma unroll
            for (int nt = 0; nt < 4; nt++)
#pragma unroll
                for (int r = 0; r < 4; r++) acc[mt][nt][r] = 0.f;

#pragma unroll
        for (int kk = 0; kk < 2; kk++) {
            uint32_t kf[2][4];
#pragma unroll
            for (int nt2 = 0; nt2 < 2; nt2++) {
                uint32_t row = wm * 32 + nt2 * 16 + (lane & 7) + ((lane >> 4) << 3);
                uint32_t chl = 2 * kk + ((lane >> 3) & 1);
                uint32_t phys = chl ^ ((row >> 1) & 3);
                ldm_x4(kf[nt2], kbase + row * 64 + phys * 16);
            }
#pragma unroll
            for (int mt = 0; mt < 2; mt++)
#pragma unroll
                for (int nt = 0; nt < 4; nt++)
                    mma16816h(acc[mt][nt], aq[mt][kk], &kf[nt >> 1][(nt & 1) * 2]);
        }

        // epilogue: exp + quantize into padded smem tile; L from quantized p.
#pragma unroll
        for (int mt = 0; mt < 2; mt++) {
            const int r0 = wn * 32 + mt * 16 + (lane >> 2);    // tile-local row
#pragma unroll
            for (int nt = 0; nt < 4; nt++) {
                const int colw = wm * 16 + nt * 4 + (lane & 3);  // half2 word in row
                float e0 = __expf(acc[mt][nt][0] - SHIFT_);
                float e1 = __expf(acc[mt][nt][1] - SHIFT_);
                float e2 = __expf(acc[mt][nt][2] - SHIFT_);
                float e3 = __expf(acc[mt][nt][3] - SHIFT_);
                __half2 p01 = __floats2half2_rn(e0, e1);
                __half2 p23 = __floats2half2_rn(e2, e3);
                Lp[mt * 2 + 0] += __low2float(p01) + __high2float(p01);
                Lp[mt * 2 + 1] += __low2float(p23) + __high2float(p23);
                sPt[r0 * 68 + colw]       = *(uint32_t*)&p01;
                sPt[(r0 + 8) * 68 + colw] = *(uint32_t*)&p23;
            }
        }
        __syncthreads();

        // cooperative coalesced copy: 64 rows x 128 halves -> g_P
        {
            const size_t rbase = ((size_t)b * N_ + n0) * N_ + kt * 128;
#pragma unroll
            for (int i = 0; i < 4; i++) {
                int id = tid + i * 256;
                int row = id >> 4, seg = id & 15;
                uint4 v = *(uint4*)(sPt + row * 68 + seg * 4);
                *(uint4*)(g_P + rbase + (size_t)row * N_ + seg * 8) = v;
            }
        }
        __syncthreads();
    }

#pragma unroll
    for (int i = 0; i < 4; i++) {
        Lp[i] += __shfl_xor_sync(0xffffffffu, Lp[i], 1);
        Lp[i] += __shfl_xor_sync(0xffffffffu, Lp[i], 2);
    }
    if ((lane & 3) == 0) {
        int rbase = wn * 32 + (lane >> 2);
        atomicAdd(&smL[rbase + 0],  Lp[0]);
        atomicAdd(&smL[rbase + 8],  Lp[1]);
        atomicAdd(&smL[rbase + 16], Lp[2]);
        atomicAdd(&smL[rbase + 24], Lp[3]);
    }
    __syncthreads();
    if (tid < 64) g_L[b * N_ + n0 + tid] = smL[tid];
}

// ---------------------------------------------------------------------------
// Kernel 3: AV GEMM fp16, CTA 128x128 / 128 thr / warp tile 64x64,
// 4-stage cp.async.  (unchanged from R12)
// ---------------------------------------------------------------------------
#define AV_OFF0   1024
#define AV_STAGE  16384
#define AV_TOTAL  (AV_OFF0 + 4 * AV_STAGE)
#define NKT       (N_ / 32)

__device__ __forceinline__ void av_load_stage(uint32_t sbase,
                                              const char* gV, const char* gP,
                                              int kt, int tid) {
    const size_t gcol = (size_t)kt * 64;
#pragma unroll
    for (int i = 0; i < 4; i++) {
        int id  = tid + i * 128;
        int row = id >> 2, ch = id & 3;
        int phys = ch ^ ((row >> 1) & 3);
        uint32_t so = row * 64 + phys * 16;
        size_t   go = (size_t)row * (N_ * 2) + gcol + ch * 16;
        cp16(sbase + so,        gV + go);
        cp16(sbase + 8192 + so, gP + go);
    }
}

__global__ __launch_bounds__(128, 2)
void av_gemm_kernel(const float* __restrict__ x, float* __restrict__ out) {
    extern __shared__ char dsm[];
    const uint32_t sb = smem_u32(dsm);
    const int tid  = threadIdx.x;
    const int wid  = tid >> 5;
    const int lane = tid & 31;
    const int wr   = wid & 1;
    const int wc   = wid >> 1;
    const int n0 = blockIdx.x * 128;
    const int c0 = blockIdx.y * 128;
    const int b  = blockIdx.z;

    float* sm_inv = (float*)dsm;
    sm_inv[tid] = 1.0f / g_L[b * N_ + n0 + tid];

    const char* gV = (const char*)g_Vf + ((size_t)(b * C_ + c0)) * N_ * 2;
    const char* gP = (const char*)g_P  + ((size_t)b * N_ + n0) * N_ * 2;

    uint32_t rowA[4], swzA[4];
#pragma unroll
    for (int mt = 0; mt < 4; mt++) {
        rowA[mt] = wr * 64 + mt * 16 + (lane & 15);
        swzA[mt] = (rowA[mt] >> 1) & 3;
    }
    const uint32_t khA = lane >> 4;
    uint32_t rowB[4], swzB[4];
#pragma unroll
    for (int nt2 = 0; nt2 < 4; nt2++) {
        rowB[nt2] = wc * 64 + nt2 * 16 + (lane & 7) + ((lane >> 4) << 3);
        swzB[nt2] = (rowB[nt2] >> 1) & 3;
    }
    const uint32_t khB = (lane >> 3) & 1;

    float acc[4][8][4];
#pragma unroll
    for (int mt = 0; mt < 4; mt++)
#pragma unroll
        for (int nt = 0; nt < 8; nt++)
#pragma unroll
            for (int r = 0; r < 4; r++) acc[mt][nt][r] = 0.f;

    av_load_stage(sb + AV_OFF0,                gV, gP, 0, tid); cp_commit();
    av_load_stage(sb + AV_OFF0 +     AV_STAGE, gV, gP, 1, tid); cp_commit();
    av_load_stage(sb + AV_OFF0 + 2 * AV_STAGE, gV, gP, 2, tid); cp_commit();

    for (int kt = 0; kt < NKT; kt++) {
        cp_wait2();
        __syncthreads();
        if (kt + 3 < NKT)
            av_load_stage(sb + AV_OFF0 + ((kt + 3) & 3) * AV_STAGE, gV, gP, kt + 3, tid);
        cp_commit();

        const uint32_t buf = sb + AV_OFF0 + (kt & 3) * AV_STAGE;
#pragma unroll
        for (int ks = 0; ks < 2; ks++) {
            uint32_t bb[4][4];
#pragma unroll
            for (int nt2 = 0; nt2 < 4; nt2++) {
                uint32_t ch = ((ks * 2 + khB) ^ swzB[nt2]) * 16;
                ldm_x4(bb[nt2], buf + 8192 + rowB[nt2] * 64 + ch);
            }
            uint32_t aa[4][4];
#pragma unroll
            for (int mt = 0; mt < 4; mt++) {
                uint32_t ch = ((ks * 2 + khA) ^ swzA[mt]) * 16;
                ldm_x4(aa[mt], buf + rowA[mt] * 64 + ch);
            }
#pragma unroll
            for (int mt = 0; mt < 4; mt++)
#pragma unroll
                for (int nt = 0; nt < 8; nt++)
                    mma16816h(acc[mt][nt], aa[mt], &bb[nt >> 1][(nt & 1) * 2]);
        }
    }

#pragma unroll
    for (int mt = 0; mt < 4; mt++) {
        int cA = c0 + wr * 64 + mt * 16 + (lane >> 2);
#pragma unroll
        for (int nt = 0; nt < 8; nt++) {
            int nl = wc * 64 + nt * 8 + (lane & 3) * 2;
            float i0 = sm_inv[nl], i1 = sm_inv[nl + 1];
            size_t o0 = ((size_t)(b * C_ + cA)) * N_ + n0 + nl;
            float2 xv = *(const float2*)(x + o0);
            float2 ov;
            ov.x = acc[mt][nt][0] * i0 + xv.x;
            ov.y = acc[mt][nt][1] * i1 + xv.y;
            *(float2*)(out + o0) = ov;
            size_t o1 = o0 + (size_t)8 * N_;
            float2 xv2 = *(const float2*)(x + o1);
            float2 ov2;
            ov2.x = acc[mt][nt][2] * i0 + xv2.x;
            ov2.y = acc[mt][nt][3] * i1 + xv2.y;
            *(float2*)(out + o1) = ov2;
        }
    }
}

// ---------------------------------------------------------------------------
extern "C" void kernel_launch(void* const* d_in, const int* in_sizes, int n_in,
                              void* d_out, int out_size) {
    const float* x  = (const float*)d_in[0];
    const float* Wq = (const float*)d_in[1];
    const float* bq = (const float*)d_in[2];
    const float* Wk = (const float*)d_in[3];
    const float* bk = (const float*)d_in[4];
    const float* Wv = (const float*)d_in[5];
    const float* bv = (const float*)d_in[6];
    float* out = (float*)d_out;

    cudaFuncSetAttribute(qkv_gemm_kernel, cudaFuncAttributeMaxDynamicSharedMemorySize, G_TOTAL);
    cudaFuncSetAttribute(scores_p_kernel, cudaFuncAttributeMaxDynamicSharedMemorySize, S_TOTAL);
    cudaFuncSetAttribute(av_gemm_kernel,  cudaFuncAttributeMaxDynamicSharedMemorySize, AV_TOTAL);

    wconv_kernel<<<320, 256>>>(Wq, bq, Wk, bk, Wv, bv);
    xconv_kernel<<<dim3(N_ / 32, C_ / 32, B_), 256>>>(x);
    qkv_gemm_kernel<<<dim3(N_ / 128, 5, B_), 256, G_TOTAL>>>();
    scores_p_kernel<<<dim3(N_ / 64, B_), 256, S_TOTAL>>>();
    av_gemm_kernel<<<dim3(N_ / 128, C_ / 128, B_), 128, AV_TOTAL>>>(x, out);
}

// round 17
// speedup vs baseline: 2.5457x; 1.0545x over previous
#include <cuda_runtime.h>
#include <cuda_fp16.h>
#include <cstdint>

#define B_ 8
#define C_ 256
#define D_ 32
#define N_ 4096

#define LOG2E   1.4426950408889634f
#define SHIFT2  23.083120654223414f    // 16 * log2(e)

// ---------------------------------------------------------------------------
// Scratch (allocation-free rule: __device__ globals)
// ---------------------------------------------------------------------------
__device__ __half  g_W16[320 * C_];               // rows: 0-31 Wq, 32-63 Wk, 64-319 Wv
__device__ float   g_bias[320];                   // bq | bk | bv
__device__ __half  g_Qf[(size_t)B_ * N_ * D_];    // [b][n][d] fp16
__device__ __half  g_Kf[(size_t)B_ * N_ * D_];    // [b][m][d] fp16, pre-scaled by log2e
__device__ __half  g_Vf[(size_t)B_ * C_ * N_];    // [b][c][m] fp16
__device__ __half  g_P[(size_t)B_ * N_ * N_];     // [b][n][m] exp(s-16) fp16
__device__ float   g_L[B_ * N_];                  // row sum (raw fp32 exp)

// ---------------------------------------------------------------------------
// Portable PTX helpers
// ---------------------------------------------------------------------------
__device__ __forceinline__ uint32_t smem_u32(const void* p) {
    uint32_t a;
    asm("{ .reg .u64 t; cvta.to.shared.u64 t, %1; cvt.u32.u64 %0, t; }" : "=r"(a) : "l"(p));
    return a;
}
__device__ __forceinline__ void cp16(uint32_t s, const void* g) {
    asm volatile("cp.async.cg.shared.global [%0], [%1], 16;" :: "r"(s), "l"(g));
}
__device__ __forceinline__ void cp_commit() {
    asm volatile("cp.async.commit_group;" ::: "memory");
}
__device__ __forceinline__ void cp_wait0() {
    asm volatile("cp.async.wait_group 0;" ::: "memory");
}
__device__ __forceinline__ void cp_wait1() {
    asm volatile("cp.async.wait_group 1;" ::: "memory");
}
__device__ __forceinline__ void cp_wait2() {
    asm volatile("cp.async.wait_group 2;" ::: "memory");
}
__device__ __forceinline__ void ldm_x4(uint32_t* r, uint32_t addr) {
    asm volatile("ldmatrix.sync.aligned.m8n8.x4.shared.b16 {%0,%1,%2,%3}, [%4];"
                 : "=r"(r[0]), "=r"(r[1]), "=r"(r[2]), "=r"(r[3]) : "r"(addr));
}
__device__ __forceinline__ void mma16816h(float* d, const uint32_t* a, const uint32_t* b) {
    asm volatile(
        "mma.sync.aligned.m16n8k16.row.col.f32.f16.f16.f32 "
        "{%0,%1,%2,%3}, {%4,%5,%6,%7}, {%8,%9}, {%0,%1,%2,%3};"
        : "+f"(d[0]), "+f"(d[1]), "+f"(d[2]), "+f"(d[3])
        : "r"(a[0]), "r"(a[1]), "r"(a[2]), "r"(a[3]), "r"(b[0]), "r"(b[1]));
}
__device__ __forceinline__ float ex2f(float x) {
    float r;
    asm("ex2.approx.f32 %0, %1;" : "=f"(r) : "f"(x));
    return r;
}

// ---------------------------------------------------------------------------
// Kernel 0: W / bias -> fp16 stacked [320][256].
// ---------------------------------------------------------------------------
__global__ __launch_bounds__(256)
void wconv_kernel(const float* __restrict__ Wq, const float* __restrict__ bq,
                  const float* __restrict__ Wk, const float* __restrict__ bk,
                  const float* __restrict__ Wv, const float* __restrict__ bv) {
    int idx = blockIdx.x * 256 + threadIdx.x;      // 0 .. 81919
    int row = idx >> 8, col = idx & 255;
    float w = (row < 32) ? Wq[row * C_ + col]
            : (row < 64) ? Wk[(row - 32) * C_ + col]
                         : Wv[(row - 64) * C_ + col];
    g_W16[idx] = __float2half_rn(w);
    if (idx < 320) {
        g_bias[idx] = (idx < 32) ? bq[idx] : (idx < 64) ? bk[idx - 32] : bv[idx - 64];
    }
}

// ---------------------------------------------------------------------------
// Kernel 1: fused x-convert + QKV projection GEMM (HMMA fp16).
// One CTA per (n-block 128, batch). Phase 1: x fp32 -> persistent swizzled
// fp16 B-tile (128n x 256c) in smem, converted ONCE. Phase 2: loop 5 e-blocks
// x 8 k-chunks, A (weights) double-buffered. K rows pre-scaled by log2e.
// smem: [0,64K) B-tile (8 chunks x 8192B); [64K,96K) staging:
//   phase1 = x fp32 double buffer (2x16KB); phase2 = A double buffer (2x4KB)
//   at +0, Q/K transpose tile at +8192.
// ---------------------------------------------------------------------------
#define QG_B     0
#define QG_X     65536
#define QG_TOTAL (65536 + 32768)

__global__ __launch_bounds__(256, 2)
void qkv_gemm_kernel(const float* __restrict__ x) {
    extern __shared__ char gsm[];
    const uint32_t sb = smem_u32(gsm);
    const int b   = blockIdx.y;
    const int n0  = blockIdx.x * 128;
    const int tid = threadIdx.x;
    const int lane = tid & 31;
    const int wm  = (tid >> 5) & 1;     // e half (32)
    const int wn  = tid >> 6;           // n quarter (32)

    // ---------------- Phase 1: x -> fp16 B-tile (once) ----------------
    const float* gx = x + (size_t)b * C_ * N_ + n0;
    {
        // load c-chunk cc (32 rows x 512B) into staging buffer bufsel
        auto load_x = [&](int bufsel, int cc) {
#pragma unroll
            for (int j = 0; j < 4; j++) {
                int id = tid + j * 256;
                int row = id >> 5, ch = id & 31;
                cp16(sb + QG_X + bufsel * 16384 + row * 512 + ch * 16,
                     (const char*)(gx + (size_t)(cc * 32 + row) * N_) + ch * 16);
            }
            cp_commit();
        };
        load_x(0, 0);
        const int n = tid & 127;          // this thread's n within tile
        const int chalf = tid >> 7;       // 16-c half within a 32-c chunk
        for (int cc = 0; cc < 8; cc++) {
            if (cc + 1 < 8) { load_x((cc + 1) & 1, cc + 1); cp_wait1(); }
            else            { cp_wait0(); }
            __syncthreads();
            const float* s32 = (const float*)(gsm + QG_X + (cc & 1) * 16384);
#pragma unroll
            for (int cp = 0; cp < 8; cp++) {
                int cl = chalf * 16 + cp * 2;             // c pair within chunk
                __half2 h = __floats2half2_rn(s32[cl * 128 + n], s32[(cl + 1) * 128 + n]);
                int chunk16 = cl >> 3;
                int phys = chunk16 ^ ((n >> 1) & 3);
                *(__half2*)(gsm + QG_B + cc * 8192 + n * 64 + phys * 16 + ((cl * 2) & 15)) = h;
            }
            __syncthreads();
        }
    }

    // ---------------- Phase 2: 5 e-blocks x 8 k-chunks ----------------
    auto load_a = [&](uint32_t sbase, int e0, int kt) {
        int row = tid >> 2, ch = tid & 3;
        int phys = ch ^ ((row >> 1) & 3);
        const char* gA = (const char*)g_W16 + (size_t)e0 * C_ * 2;
        cp16(sbase + row * 64 + phys * 16, gA + (size_t)row * 512 + kt * 64 + ch * 16);
        cp_commit();
    };

    for (int e0i = 0; e0i < 5; e0i++) {
        const int e0 = e0i * 64;
        load_a(sb + QG_X, e0, 0);

        float acc[2][4][4];
#pragma unroll
        for (int mt = 0; mt < 2; mt++)
#pragma unroll
            for (int nt = 0; nt < 4; nt++)
#pragma unroll
                for (int r = 0; r < 4; r++) acc[mt][nt][r] = 0.f;

        for (int kt = 0; kt < 8; kt++) {
            if (kt + 1 < 8) { load_a(sb + QG_X + ((kt + 1) & 1) * 4096, e0, kt + 1); cp_wait1(); }
            else            { cp_wait0(); }
            __syncthreads();

            const uint32_t abase = sb + QG_X + (kt & 1) * 4096;
            const uint32_t bbase = sb + QG_B + kt * 8192;
#pragma unroll
            for (int ks = 0; ks < 2; ks++) {
                uint32_t af[2][4];
#pragma unroll
                for (int mt = 0; mt < 2; mt++) {
                    uint32_t row = wm * 32 + mt * 16 + (lane & 15);
                    uint32_t chl = ks * 2 + (lane >> 4);
                    uint32_t phys = chl ^ ((row >> 1) & 3);
                    ldm_x4(af[mt], abase + row * 64 + phys * 16);
                }
                uint32_t bf[2][4];
#pragma unroll
                for (int nt2 = 0; nt2 < 2; nt2++) {
                    uint32_t row = wn * 32 + nt2 * 16 + (lane & 7) + ((lane >> 4) << 3);
                    uint32_t chl = ks * 2 + ((lane >> 3) & 1);
                    uint32_t phys = chl ^ ((row >> 1) & 3);
                    ldm_x4(bf[nt2], bbase + row * 64 + phys * 16);
                }
#pragma unroll
                for (int mt = 0; mt < 2; mt++)
#pragma unroll
                    for (int nt = 0; nt < 4; nt++)
                        mma16816h(acc[mt][nt], af[mt], &bf[nt >> 1][(nt & 1) * 2]);
            }
            __syncthreads();
        }

        if (e0 >= 64) {
            // V rows: direct store to g_Vf [c][n], c = e - 64.
#pragma unroll
            for (int mt = 0; mt < 2; mt++) {
#pragma unroll
                for (int half_ = 0; half_ < 2; half_++) {
                    int eloc = wm * 32 + mt * 16 + (lane >> 2) + half_ * 8;
                    float bias = g_bias[e0 + eloc];
                    int c = e0 - 64 + eloc;
                    __half* dst = g_Vf + ((size_t)(b * C_ + c)) * N_ + n0;
#pragma unroll
                    for (int nt = 0; nt < 4; nt++) {
                        int nl = wn * 32 + nt * 8 + (lane & 3) * 2;
                        __half2 h = __floats2half2_rn(acc[mt][nt][half_ * 2 + 0] + bias,
                                                      acc[mt][nt][half_ * 2 + 1] + bias);
                        *(__half2*)(dst + nl) = h;
                    }
                }
            }
        } else {
            // Q/K: stage tile, K rows (eloc>=32) pre-scaled by log2e.
            __half* smt = (__half*)(gsm + QG_X + 8192);     // [64][132]
#pragma unroll
            for (int mt = 0; mt < 2; mt++) {
#pragma unroll
                for (int half_ = 0; half_ < 2; half_++) {
                    int eloc = wm * 32 + mt * 16 + (lane >> 2) + half_ * 8;
                    float bias = g_bias[e0 + eloc];
                    float scale = (eloc >= 32) ? LOG2E : 1.0f;
#pragma unroll
                    for (int nt = 0; nt < 4; nt++) {
                        int nl = wn * 32 + nt * 8 + (lane & 3) * 2;
                        smt[eloc * 132 + nl]     = __float2half_rn((acc[mt][nt][half_ * 2 + 0] + bias) * scale);
                        smt[eloc * 132 + nl + 1] = __float2half_rn((acc[mt][nt][half_ * 2 + 1] + bias) * scale);
                    }
                }
            }
            __syncthreads();
            const int n = tid >> 1;          // 0..127
            const int h = tid & 1;           // 0 = Q, 1 = K
            __half row16[32];
#pragma unroll
            for (int d = 0; d < 32; d++) row16[d] = smt[(h * 32 + d) * 132 + n];
            __half* dst = (h == 0 ? g_Qf : g_Kf) + ((size_t)(b * N_ + n0 + n)) * 32;
            *(uint4*)(dst)      = *(uint4*)(row16);
            *(uint4*)(dst + 8)  = *(uint4*)(row16 + 8);
            *(uint4*)(dst + 16) = *(uint4*)(row16 + 16);
            *(uint4*)(dst + 24) = *(uint4*)(row16 + 24);
            __syncthreads();
        }
    }
}

// ---------------------------------------------------------------------------
// Kernel 2: HMMA fp16 scores + ex2 + quantize + L (raw fp32 sum).
// K pre-scaled by log2e -> p = ex2(acc - 16*log2e). Coalesced P via smem tile.
// ---------------------------------------------------------------------------
#define S_NIT   (N_ / 128)
#define SO_Q    512
#define SO_K    (SO_Q + 4096)
#define SO_T    (SO_K + 2 * 8192)            // P staging tile
#define S_TOTAL (SO_T + 64 * 136 * 2)

__device__ __forceinline__ void s_load_k(uint32_t sbase, int b, int m0, int tid) {
    const char* gk = (const char*)g_Kf + ((size_t)b * N_ + m0) * 64;
#pragma unroll
    for (int i = 0; i < 2; i++) {
        int id = tid + i * 256;
        int row = id >> 2, ch = id & 3;
        int phys = ch ^ ((row >> 1) & 3);
        cp16(sbase + row * 64 + phys * 16, gk + row * 64 + ch * 16);
    }
}

__global__ __launch_bounds__(256, 3)
void scores_p_kernel() {
    extern __shared__ char ssm[];
    const uint32_t sb = smem_u32(ssm);
    float* smL = (float*)ssm;
    uint32_t* sPt = (uint32_t*)(ssm + SO_T);     // [64 rows][68 words]
    const int b    = blockIdx.y;
    const int n0   = blockIdx.x * 64;
    const int tid  = threadIdx.x;
    const int lane = tid & 31;
    const int wn   = (tid >> 5) & 1;
    const int wm   = tid >> 6;

    if (tid < 64) smL[tid] = 0.f;

    {
        int row = tid >> 2, ch = tid & 3;
        int phys = ch ^ ((row >> 1) & 3);
        const char* gq = (const char*)g_Qf + ((size_t)b * N_ + n0) * 64;
        cp16(sb + SO_Q + row * 64 + phys * 16, gq + row * 64 + ch * 16);
    }
    s_load_k(sb + SO_K, b, 0, tid);
    cp_commit();
    cp_wait0();
    __syncthreads();

    uint32_t aq[2][2][4];
#pragma unroll
    for (int mt = 0; mt < 2; mt++)
#pragma unroll
        for (int kk = 0; kk < 2; kk++) {
            uint32_t row = wn * 32 + mt * 16 + (lane & 15);
            uint32_t chl = 2 * kk + (lane >> 4);
            uint32_t phys = chl ^ ((row >> 1) & 3);
            ldm_x4(aq[mt][kk], sb + SO_Q + row * 64 + phys * 16);
        }

    float Lp[4] = {0.f, 0.f, 0.f, 0.f};

    for (int kt = 0; kt < S_NIT; kt++) {
        if (kt + 1 < S_NIT) {
            s_load_k(sb + SO_K + ((kt + 1) & 1) * 8192, b, (kt + 1) * 128, tid);
            cp_commit();
            cp_wait1();
        } else {
            cp_wait0();
        }
        __syncthreads();

        const uint32_t kbase = sb + SO_K + (kt & 1) * 8192;
        float acc[2][4][4];
#pragma unroll
        for (int mt = 0; mt < 2; mt++)
#pragma unroll
            for (int nt = 0; nt < 4; nt++)
#pragma unroll
                for (int r = 0; r < 4; r++) acc[mt][nt][r] = 0.f;

#pragma unroll
        for (int kk = 0; kk < 2; kk++) {
            uint32_t kf[2][4];
#pragma unroll
            for (int nt2 = 0; nt2 < 2; nt2++) {
                uint32_t row = wm * 32 + nt2 * 16 + (lane & 7) + ((lane >> 4) << 3);
                uint32_t chl = 2 * kk + ((lane >> 3) & 1);
                uint32_t phys = chl ^ ((row >> 1) & 3);
                ldm_x4(kf[nt2], kbase + row * 64 + phys * 16);
            }
#pragma unroll
            for (int mt = 0; mt < 2; mt++)
#pragma unroll
                for (int nt = 0; nt < 4; nt++)
                    mma16816h(acc[mt][nt], aq[mt][kk], &kf[nt >> 1][(nt & 1) * 2]);
        }

        // epilogue: ex2 + quantize into padded smem tile; L from raw fp32.
#pragma unroll
        for (int mt = 0; mt < 2; mt++) {
            const int r0 = wn * 32 + mt * 16 + (lane >> 2);
#pragma unroll
            for (int nt = 0; nt < 4; nt++) {
                const int colw = wm * 16 + nt * 4 + (lane & 3);
                float e0 = ex2f(acc[mt][nt][0] - SHIFT2);
                float e1 = ex2f(acc[mt][nt][1] - SHIFT2);
                float e2 = ex2f(acc[mt][nt][2] - SHIFT2);
                float e3 = ex2f(acc[mt][nt][3] - SHIFT2);
                __half2 p01 = __floats2half2_rn(e0, e1);
                __half2 p23 = __floats2half2_rn(e2, e3);
                Lp[mt * 2 + 0] += e0 + e1;
                Lp[mt * 2 + 1] += e2 + e3;
                sPt[r0 * 68 + colw]       = *(uint32_t*)&p01;
                sPt[(r0 + 8) * 68 + colw] = *(uint32_t*)&p23;
            }
        }
        __syncthreads();

        // cooperative coalesced copy: 64 rows x 128 halves -> g_P
        {
            const size_t rbase = ((size_t)b * N_ + n0) * N_ + kt * 128;
#pragma unroll
            for (int i = 0; i < 4; i++) {
                int id = tid + i * 256;
                int row = id >> 4, seg = id & 15;
                uint4 v = *(uint4*)(sPt + row * 68 + seg * 4);
                *(uint4*)(g_P + rbase + (size_t)row * N_ + seg * 8) = v;
            }
        }
        __syncthreads();
    }

#pragma unroll
    for (int i = 0; i < 4; i++) {
        Lp[i] += __shfl_xor_sync(0xffffffffu, Lp[i], 1);
        Lp[i] += __shfl_xor_sync(0xffffffffu, Lp[i], 2);
    }
    if ((lane & 3) == 0) {
        int rbase = wn * 32 + (lane >> 2);
        atomicAdd(&smL[rbase + 0],  Lp[0]);
        atomicAdd(&smL[rbase + 8],  Lp[1]);
        atomicAdd(&smL[rbase + 16], Lp[2]);
        atomicAdd(&smL[rbase + 24], Lp[3]);
    }
    __syncthreads();
    if (tid < 64) g_L[b * N_ + n0 + tid] = smL[tid];
}

// ---------------------------------------------------------------------------
// Kernel 3: AV GEMM fp16, CTA 128x128 / 128 thr / warp tile 64x64,
// 4-stage cp.async.  (unchanged from R12)
// ---------------------------------------------------------------------------
#define AV_OFF0   1024
#define AV_STAGE  16384
#define AV_TOTAL  (AV_OFF0 + 4 * AV_STAGE)
#define NKT       (N_ / 32)

__device__ __forceinline__ void av_load_stage(uint32_t sbase,
                                              const char* gV, const char* gP,
                                              int kt, int tid) {
    const size_t gcol = (size_t)kt * 64;
#pragma unroll
    for (int i = 0; i < 4; i++) {
        int id  = tid + i * 128;
        int row = id >> 2, ch = id & 3;
        int phys = ch ^ ((row >> 1) & 3);
        uint32_t so = row * 64 + phys * 16;
        size_t   go = (size_t)row * (N_ * 2) + gcol + ch * 16;
        cp16(sbase + so,        gV + go);
        cp16(sbase + 8192 + so, gP + go);
    }
}

__global__ __launch_bounds__(128, 2)
void av_gemm_kernel(const float* __restrict__ x, float* __restrict__ out) {
    extern __shared__ char dsm[];
    const uint32_t sb = smem_u32(dsm);
    const int tid  = threadIdx.x;
    const int wid  = tid >> 5;
    const int lane = tid & 31;
    const int wr   = wid & 1;
    const int wc   = wid >> 1;
    const int n0 = blockIdx.x * 128;
    const int c0 = blockIdx.y * 128;
    const int b  = blockIdx.z;

    float* sm_inv = (float*)dsm;
    sm_inv[tid] = 1.0f / g_L[b * N_ + n0 + tid];

    const char* gV = (const char*)g_Vf + ((size_t)(b * C_ + c0)) * N_ * 2;
    const char* gP = (const char*)g_P  + ((size_t)b * N_ + n0) * N_ * 2;

    uint32_t rowA[4], swzA[4];
#pragma unroll
    for (int mt = 0; mt < 4; mt++) {
        rowA[mt] = wr * 64 + mt * 16 + (lane & 15);
        swzA[mt] = (rowA[mt] >> 1) & 3;
    }
    const uint32_t khA = lane >> 4;
    uint32_t rowB[4], swzB[4];
#pragma unroll
    for (int nt2 = 0; nt2 < 4; nt2++) {
        rowB[nt2] = wc * 64 + nt2 * 16 + (lane & 7) + ((lane >> 4) << 3);
        swzB[nt2] = (rowB[nt2] >> 1) & 3;
    }
    const uint32_t khB = (lane >> 3) & 1;

    float acc[4][8][4];
#pragma unroll
    for (int mt = 0; mt < 4; mt++)
#pragma unroll
        for (int nt = 0; nt < 8; nt++)
#pragma unroll
            for (int r = 0; r < 4; r++) acc[mt][nt][r] = 0.f;

    av_load_stage(sb + AV_OFF0,                gV, gP, 0, tid); cp_commit();
    av_load_stage(sb + AV_OFF0 +     AV_STAGE, gV, gP, 1, tid); cp_commit();
    av_load_stage(sb + AV_OFF0 + 2 * AV_STAGE, gV, gP, 2, tid); cp_commit();

    for (int kt = 0; kt < NKT; kt++) {
        cp_wait2();
        __syncthreads();
        if (kt + 3 < NKT)
            av_load_stage(sb + AV_OFF0 + ((kt + 3) & 3) * AV_STAGE, gV, gP, kt + 3, tid);
        cp_commit();

        const uint32_t buf = sb + AV_OFF0 + (kt & 3) * AV_STAGE;
#pragma unroll
        for (int ks = 0; ks < 2; ks++) {
            uint32_t bb[4][4];
#pragma unroll
            for (int nt2 = 0; nt2 < 4; nt2++) {
                uint32_t ch = ((ks * 2 + khB) ^ swzB[nt2]) * 16;
                ldm_x4(bb[nt2], buf + 8192 + rowB[nt2] * 64 + ch);
            }
            uint32_t aa[4][4];
#pragma unroll
            for (int mt = 0; mt < 4; mt++) {
                uint32_t ch = ((ks * 2 + khA) ^ swzA[mt]) * 16;
                ldm_x4(aa[mt], buf + rowA[mt] * 64 + ch);
            }
#pragma unroll
            for (int mt = 0; mt < 4; mt++)
#pragma unroll
                for (int nt = 0; nt < 8; nt++)
                    mma16816h(acc[mt][nt], aa[mt], &bb[nt >> 1][(nt & 1) * 2]);
        }
    }

#pragma unroll
    for (int mt = 0; mt < 4; mt++) {
        int cA = c0 + wr * 64 + mt * 16 + (lane >> 2);
#pragma unroll
        for (int nt = 0; nt < 8; nt++) {
            int nl = wc * 64 + nt * 8 + (lane & 3) * 2;
            float i0 = sm_inv[nl], i1 = sm_inv[nl + 1];
            size_t o0 = ((size_t)(b * C_ + cA)) * N_ + n0 + nl;
            float2 xv = *(const float2*)(x + o0);
            float2 ov;
            ov.x = acc[mt][nt][0] * i0 + xv.x;
            ov.y = acc[mt][nt][1] * i1 + xv.y;
            *(float2*)(out + o0) = ov;
            size_t o1 = o0 + (size_t)8 * N_;
            float2 xv2 = *(const float2*)(x + o1);
            float2 ov2;
            ov2.x = acc[mt][nt][2] * i0 + xv2.x;
            ov2.y = acc[mt][nt][3] * i1 + xv2.y;
            *(float2*)(out + o1) = ov2;
        }
    }
}

// ---------------------------------------------------------------------------
extern "C" void kernel_launch(void* const* d_in, const int* in_sizes, int n_in,
                              void* d_out, int out_size) {
    const float* x  = (const float*)d_in[0];
    const float* Wq = (const float*)d_in[1];
    const float* bq = (const float*)d_in[2];
    const float* Wk = (const float*)d_in[3];
    const float* bk = (const float*)d_in[4];
    const float* Wv = (const float*)d_in[5];
    const float* bv = (const float*)d_in[6];
    float* out = (float*)d_out;

    cudaFuncSetAttribute(qkv_gemm_kernel, cudaFuncAttributeMaxDynamicSharedMemorySize, QG_TOTAL);
    cudaFuncSetAttribute(scores_p_kernel, cudaFuncAttributeMaxDynamicSharedMemorySize, S_TOTAL);
    cudaFuncSetAttribute(av_gemm_kernel,  cudaFuncAttributeMaxDynamicSharedMemorySize, AV_TOTAL);

    wconv_kernel<<<320, 256>>>(Wq, bq, Wk, bk, Wv, bv);
    qkv_gemm_kernel<<<dim3(N_ / 128, B_), 256, QG_TOTAL>>>(x);
    scores_p_kernel<<<dim3(N_ / 64, B_), 256, S_TOTAL>>>();
    av_gemm_kernel<<<dim3(N_ / 128, C_ / 128, B_), 128, AV_TOTAL>>>(x, out);
}